// round 3
// baseline (speedup 1.0000x reference)
#include <cuda_runtime.h>
#include <cstdint>
#include <cstddef>

#define NN 50000
#define EE 800000
#define NF 64
#define HID 64

// Scatter-sum accumulator (allocation-free scratch: device global)
__device__ float g_agg[NN * HID];

typedef unsigned long long ull;

__device__ __forceinline__ ull pack2(float lo, float hi) {
    ull r;
    asm("mov.b64 %0, {%1, %2};" : "=l"(r) : "r"(__float_as_uint(lo)), "r"(__float_as_uint(hi)));
    return r;
}
__device__ __forceinline__ void unpack2(ull v, float &lo, float &hi) {
    unsigned int a, b;
    asm("mov.b64 {%0, %1}, %2;" : "=r"(a), "=r"(b) : "l"(v));
    lo = __uint_as_float(a); hi = __uint_as_float(b);
}
// Packed fp32x2 FMA (sm_100+): elementwise d = a*b + c on 2 packed floats
__device__ __forceinline__ ull fma2(ull a, ull b, ull c) {
    ull d; asm("fma.rn.f32x2 %0, %1, %2, %3;" : "=l"(d) : "l"(a), "l"(b), "l"(c)); return d;
}
__device__ __forceinline__ ull relu2(ull v) {
    float a, b; unpack2(v, a, b);
    return pack2(fmaxf(a, 0.f), fmaxf(b, 0.f));
}
// Vectorized no-return global reduction (sm_90+)
__device__ __forceinline__ void red_add_v2(float* p, float a, float b) {
    asm volatile("red.global.add.v2.f32 [%0], {%1, %2};" :: "l"(p), "f"(a), "f"(b) : "memory");
}

// ---------------------------------------------------------------------------
// Zero the aggregation buffer (graph-replayed every launch)
// ---------------------------------------------------------------------------
__global__ void zero_agg_kernel() {
    int i = blockIdx.x * blockDim.x + threadIdx.x;
    const int n4 = NN * HID / 4;
    float4* p = (float4*)g_agg;
    float4 z = make_float4(0.f, 0.f, 0.f, 0.f);
    for (; i < n4; i += gridDim.x * blockDim.x) p[i] = z;
}

// ---------------------------------------------------------------------------
// Edge kernel. Block = 256 threads processes a 128-edge tile.
//   Phase A: gather h[row],h[col] + radial, 4x4 register-transpose -> xT[k][e]
//   Phase B: GEMM1 129->64 (relu), Phase C: GEMM2 64->64 (relu*mask)
//   Phase D: scatter-add to g_agg via red.global.add.v2.f32
// Thread tile: 8 edges x 4 outputs, packed f32x2 over the edge dimension.
// Weights stored duplicated {w,w} so the packed multiplier is a direct LDS.128.
//
// Smem (bytes):
//   W1d [129*64] float2 @0       (66048)
//   W2d [ 64*64] float2 @66048   (32768)
//   xT  [129*128] float @98816   (66048; reused as oT[64*128] after GEMM1)
//   h1T [ 64*128] float @164864  (32768)        total 197632
#define E_W1D_OFF 0
#define E_W2D_OFF 66048
#define E_XT_OFF  98816
#define E_H1T_OFF 164864
#define E_SMEM    197632

__global__ __launch_bounds__(256, 1) void edge_kernel(
    const float* __restrict__ h, const float* __restrict__ coord,
    const int* __restrict__ row, const int* __restrict__ col,
    const float* __restrict__ edge_mask,
    const float* __restrict__ W1, const float* __restrict__ b1,
    const float* __restrict__ W2, const float* __restrict__ b2)
{
    extern __shared__ char smem[];
    float2* W1d = (float2*)(smem + E_W1D_OFF);
    float2* W2d = (float2*)(smem + E_W2D_OFF);
    float*  xT  = (float*)(smem + E_XT_OFF);
    float*  h1T = (float*)(smem + E_H1T_OFF);
    float*  oT  = xT;   // reuse after GEMM1 consumed xT

    const int tid  = threadIdx.x;
    const int warp = tid >> 5, lane = tid & 31;
    const int blk  = blockIdx.x;
    const int e0   = blk * 128;

    // Weights, duplicated for packed multipliers
    for (int i = tid; i < 129 * 64; i += 256) { float w = W1[i]; W1d[i] = make_float2(w, w); }
    for (int i = tid; i < 64 * 64;  i += 256) { float w = W2[i]; W2d[i] = make_float2(w, w); }

    // --- Phase A: gather + register transpose ---
    {
        int4 r4 = ((const int4*)row)[blk * 32 + lane];  // edges e0+4*lane .. +3
        int4 c4 = ((const int4*)col)[blk * 32 + lane];
        #pragma unroll
        for (int it = 0; it < 4; it++) {
            int ug = warp + it * 8;            // 0..31 k-groups of 4
            bool isrow = (ug < 16);
            int kk = isrow ? 4 * ug : 4 * (ug - 16);
            int kb = isrow ? 4 * ug : 64 + 4 * (ug - 16);
            int4 s = isrow ? r4 : c4;
            float4 f0 = *(const float4*)(h + (size_t)s.x * NF + kk);
            float4 f1 = *(const float4*)(h + (size_t)s.y * NF + kk);
            float4 f2 = *(const float4*)(h + (size_t)s.z * NF + kk);
            float4 f3 = *(const float4*)(h + (size_t)s.w * NF + kk);
            *(float4*)(xT + (kb + 0) * 128 + 4 * lane) = make_float4(f0.x, f1.x, f2.x, f3.x);
            *(float4*)(xT + (kb + 1) * 128 + 4 * lane) = make_float4(f0.y, f1.y, f2.y, f3.y);
            *(float4*)(xT + (kb + 2) * 128 + 4 * lane) = make_float4(f0.z, f1.z, f2.z, f3.z);
            *(float4*)(xT + (kb + 3) * 128 + 4 * lane) = make_float4(f0.w, f1.w, f2.w, f3.w);
        }
    }
    if (tid < 128) {   // radial row k=128
        int e = e0 + tid;
        int r = row[e], c = col[e];
        float dx = coord[3 * r]     - coord[3 * c];
        float dy = coord[3 * r + 1] - coord[3 * c + 1];
        float dz = coord[3 * r + 2] - coord[3 * c + 2];
        xT[128 * 128 + tid] = dx * dx + dy * dy + dz * dz;
    }
    __syncthreads();

    const int tx = tid & 15;   // 8 edges (4 packed pairs)
    const int ty = tid >> 4;   // 4 outputs

    ull acc[4][4];

    // --- Phase B: GEMM1 (K=129), relu ---
    #pragma unroll
    for (int j = 0; j < 4; j++) {
        float bv = __ldg(b1 + 4 * ty + j);
        ull bp = pack2(bv, bv);
        #pragma unroll
        for (int i = 0; i < 4; i++) acc[i][j] = bp;
    }
    #pragma unroll 3
    for (int k = 0; k < 129; k++) {
        ulonglong2 a01 = *(const ulonglong2*)(xT + k * 128 + 8 * tx);
        ulonglong2 a23 = *(const ulonglong2*)(xT + k * 128 + 8 * tx + 4);
        ulonglong2 w01 = *(const ulonglong2*)(W1d + k * 64 + 4 * ty);
        ulonglong2 w23 = *(const ulonglong2*)(W1d + k * 64 + 4 * ty + 2);
        ull a[4] = {a01.x, a01.y, a23.x, a23.y};
        ull w[4] = {w01.x, w01.y, w23.x, w23.y};
        #pragma unroll
        for (int i = 0; i < 4; i++)
            #pragma unroll
            for (int j = 0; j < 4; j++)
                acc[i][j] = fma2(a[i], w[j], acc[i][j]);
    }
    __syncthreads();
    #pragma unroll
    for (int i = 0; i < 4; i++)
        #pragma unroll
        for (int j = 0; j < 4; j++)
            *(ull*)(h1T + (4 * ty + j) * 128 + 8 * tx + 2 * i) = relu2(acc[i][j]);
    __syncthreads();

    // --- Phase C: GEMM2 (K=64), relu ---
    #pragma unroll
    for (int j = 0; j < 4; j++) {
        float bv = __ldg(b2 + 4 * ty + j);
        ull bp = pack2(bv, bv);
        #pragma unroll
        for (int i = 0; i < 4; i++) acc[i][j] = bp;
    }
    #pragma unroll 4
    for (int k = 0; k < 64; k++) {
        ulonglong2 a01 = *(const ulonglong2*)(h1T + k * 128 + 8 * tx);
        ulonglong2 a23 = *(const ulonglong2*)(h1T + k * 128 + 8 * tx + 4);
        ulonglong2 w01 = *(const ulonglong2*)(W2d + k * 64 + 4 * ty);
        ulonglong2 w23 = *(const ulonglong2*)(W2d + k * 64 + 4 * ty + 2);
        ull a[4] = {a01.x, a01.y, a23.x, a23.y};
        ull w[4] = {w01.x, w01.y, w23.x, w23.y};
        #pragma unroll
        for (int i = 0; i < 4; i++)
            #pragma unroll
            for (int j = 0; j < 4; j++)
                acc[i][j] = fma2(a[i], w[j], acc[i][j]);
    }
    #pragma unroll
    for (int i = 0; i < 4; i++)
        #pragma unroll
        for (int j = 0; j < 4; j++)
            *(ull*)(oT + (4 * ty + j) * 128 + 8 * tx + 2 * i) = relu2(acc[i][j]);
    __syncthreads();

    // --- Phase D: mask + scatter-add (2 threads per edge, 32 feats each) ---
    {
        int e_l = tid >> 1, half = tid & 1;
        int e = e0 + e_l;
        int r = row[e];
        float em = edge_mask[e];
        float* dst = g_agg + (size_t)r * HID + half * 32;
        const float* src = oT + (half * 32) * 128 + e_l;
        #pragma unroll
        for (int jj = 0; jj < 32; jj += 2) {
            float v0 = src[(jj    ) * 128] * em;
            float v1 = src[(jj + 1) * 128] * em;
            red_add_v2(dst + jj, v0, v1);
        }
    }
}

// ---------------------------------------------------------------------------
// Node kernel. Block = 256 threads, 128-node tile. Same GEMM skeleton.
//   W1d [128*64] float2 @0 (65536) | W2d [64*64] float2 @65536 (32768)
//   xT [128*128] @98304 (65536, reused as oT) | h1T [64*128] @163840 (32768)
#define N_W1D_OFF 0
#define N_W2D_OFF 65536
#define N_XT_OFF  98304
#define N_H1T_OFF 163840
#define N_SMEM    196608

__global__ __launch_bounds__(256, 1) void node_kernel(
    const float* __restrict__ h,
    const float* __restrict__ W1, const float* __restrict__ b1,
    const float* __restrict__ W2, const float* __restrict__ b2,
    float* __restrict__ hout)
{
    extern __shared__ char smem[];
    float2* W1d = (float2*)(smem + N_W1D_OFF);
    float2* W2d = (float2*)(smem + N_W2D_OFF);
    float*  xT  = (float*)(smem + N_XT_OFF);
    float*  h1T = (float*)(smem + N_H1T_OFF);
    float*  oT  = xT;

    const int tid  = threadIdx.x;
    const int warp = tid >> 5, lane = tid & 31;
    const int n0   = blockIdx.x * 128;

    for (int i = tid; i < 128 * 64; i += 256) { float w = W1[i]; W1d[i] = make_float2(w, w); }
    for (int i = tid; i < 64 * 64;  i += 256) { float w = W2[i]; W2d[i] = make_float2(w, w); }

    // Phase A: stage [h || agg] transposed (node indices clamped for tail)
    {
        #pragma unroll
        for (int it = 0; it < 4; it++) {
            int ug = warp + it * 8;
            bool isH = (ug < 16);
            int kk = isH ? 4 * ug : 4 * (ug - 16);
            int kb = isH ? 4 * ug : 64 + 4 * (ug - 16);
            const float* src = isH ? h : g_agg;
            int na = min(n0 + 4 * lane + 0, NN - 1);
            int nb = min(n0 + 4 * lane + 1, NN - 1);
            int nc = min(n0 + 4 * lane + 2, NN - 1);
            int nd = min(n0 + 4 * lane + 3, NN - 1);
            float4 f0 = *(const float4*)(src + (size_t)na * 64 + kk);
            float4 f1 = *(const float4*)(src + (size_t)nb * 64 + kk);
            float4 f2 = *(const float4*)(src + (size_t)nc * 64 + kk);
            float4 f3 = *(const float4*)(src + (size_t)nd * 64 + kk);
            *(float4*)(xT + (kb + 0) * 128 + 4 * lane) = make_float4(f0.x, f1.x, f2.x, f3.x);
            *(float4*)(xT + (kb + 1) * 128 + 4 * lane) = make_float4(f0.y, f1.y, f2.y, f3.y);
            *(float4*)(xT + (kb + 2) * 128 + 4 * lane) = make_float4(f0.z, f1.z, f2.z, f3.z);
            *(float4*)(xT + (kb + 3) * 128 + 4 * lane) = make_float4(f0.w, f1.w, f2.w, f3.w);
        }
    }
    __syncthreads();

    const int tx = tid & 15;
    const int ty = tid >> 4;
    ull acc[4][4];

    // GEMM1 K=128, relu
    #pragma unroll
    for (int j = 0; j < 4; j++) {
        float bv = __ldg(b1 + 4 * ty + j);
        ull bp = pack2(bv, bv);
        #pragma unroll
        for (int i = 0; i < 4; i++) acc[i][j] = bp;
    }
    #pragma unroll 4
    for (int k = 0; k < 128; k++) {
        ulonglong2 a01 = *(const ulonglong2*)(xT + k * 128 + 8 * tx);
        ulonglong2 a23 = *(const ulonglong2*)(xT + k * 128 + 8 * tx + 4);
        ulonglong2 w01 = *(const ulonglong2*)(W1d + k * 64 + 4 * ty);
        ulonglong2 w23 = *(const ulonglong2*)(W1d + k * 64 + 4 * ty + 2);
        ull a[4] = {a01.x, a01.y, a23.x, a23.y};
        ull w[4] = {w01.x, w01.y, w23.x, w23.y};
        #pragma unroll
        for (int i = 0; i < 4; i++)
            #pragma unroll
            for (int j = 0; j < 4; j++)
                acc[i][j] = fma2(a[i], w[j], acc[i][j]);
    }
    __syncthreads();
    #pragma unroll
    for (int i = 0; i < 4; i++)
        #pragma unroll
        for (int j = 0; j < 4; j++)
            *(ull*)(h1T + (4 * ty + j) * 128 + 8 * tx + 2 * i) = relu2(acc[i][j]);
    __syncthreads();

    // GEMM2 K=64 (no relu)
    #pragma unroll
    for (int j = 0; j < 4; j++) {
        float bv = __ldg(b2 + 4 * ty + j);
        ull bp = pack2(bv, bv);
        #pragma unroll
        for (int i = 0; i < 4; i++) acc[i][j] = bp;
    }
    #pragma unroll 4
    for (int k = 0; k < 64; k++) {
        ulonglong2 a01 = *(const ulonglong2*)(h1T + k * 128 + 8 * tx);
        ulonglong2 a23 = *(const ulonglong2*)(h1T + k * 128 + 8 * tx + 4);
        ulonglong2 w01 = *(const ulonglong2*)(W2d + k * 64 + 4 * ty);
        ulonglong2 w23 = *(const ulonglong2*)(W2d + k * 64 + 4 * ty + 2);
        ull a[4] = {a01.x, a01.y, a23.x, a23.y};
        ull w[4] = {w01.x, w01.y, w23.x, w23.y};
        #pragma unroll
        for (int i = 0; i < 4; i++)
            #pragma unroll
            for (int j = 0; j < 4; j++)
                acc[i][j] = fma2(a[i], w[j], acc[i][j]);
    }
    #pragma unroll
    for (int i = 0; i < 4; i++)
        #pragma unroll
        for (int j = 0; j < 4; j++)
            *(ull*)(oT + (4 * ty + j) * 128 + 8 * tx + 2 * i) = acc[i][j];
    __syncthreads();

    // Residual + coalesced stores
    {
        int n_l = tid >> 1, half = tid & 1;
        int n = n0 + n_l;
        if (n < NN) {
            const float* hr = h + (size_t)n * NF + half * 32;
            float* orow = hout + (size_t)n * NF + half * 32;
            const float* src = oT + (half * 32) * 128 + n_l;
            #pragma unroll
            for (int jj = 0; jj < 32; jj += 4) {
                float4 hv = *(const float4*)(hr + jj);
                float4 o;
                o.x = src[(jj    ) * 128] + hv.x;
                o.y = src[(jj + 1) * 128] + hv.y;
                o.z = src[(jj + 2) * 128] + hv.z;
                o.w = src[(jj + 3) * 128] + hv.w;
                *(float4*)(orow + jj) = o;
            }
        }
    }
}

// ---------------------------------------------------------------------------
extern "C" void kernel_launch(void* const* d_in, const int* in_sizes, int n_in,
                              void* d_out, int out_size) {
    const float* h         = (const float*)d_in[0];
    const float* coord     = (const float*)d_in[1];
    const int*   row       = (const int*)d_in[2];
    const int*   col       = (const int*)d_in[3];
    // d_in[4] = node_mask (unused on the reference path)
    const float* edge_mask = (const float*)d_in[5];
    const float* W_e1 = (const float*)d_in[6];
    const float* b_e1 = (const float*)d_in[7];
    const float* W_e2 = (const float*)d_in[8];
    const float* b_e2 = (const float*)d_in[9];
    const float* W_n1 = (const float*)d_in[10];
    const float* b_n1 = (const float*)d_in[11];
    const float* W_n2 = (const float*)d_in[12];
    const float* b_n2 = (const float*)d_in[13];
    float* out = (float*)d_out;

    // Unconditional (no static state): host-side attribute set, capture-safe.
    cudaFuncSetAttribute(edge_kernel, cudaFuncAttributeMaxDynamicSharedMemorySize, E_SMEM);
    cudaFuncSetAttribute(node_kernel, cudaFuncAttributeMaxDynamicSharedMemorySize, N_SMEM);

    zero_agg_kernel<<<512, 256>>>();
    edge_kernel<<<EE / 128, 256, E_SMEM>>>(h, coord, row, col, edge_mask,
                                           W_e1, b_e1, W_e2, b_e2);
    node_kernel<<<(NN + 127) / 128, 256, N_SMEM>>>(h, W_n1, b_n1, W_n2, b_n2, out);
    cudaMemcpyAsync(out + (size_t)NN * NF, coord, (size_t)NN * 3 * sizeof(float),
                    cudaMemcpyDeviceToDevice, 0);
}

// round 5
// speedup vs baseline: 1.5954x; 1.5954x over previous
#include <cuda_runtime.h>
#include <cstdint>
#include <cstddef>

#define NN 50000
#define EE 800000
#define NF 64
#define HID 64
#define NTILES (EE / 128)

// Scatter-sum accumulator (allocation-free scratch: device global)
__device__ float g_agg[NN * HID];

typedef unsigned long long ull;

__device__ __forceinline__ ull pack2(float lo, float hi) {
    ull r;
    asm("mov.b64 %0, {%1, %2};" : "=l"(r) : "r"(__float_as_uint(lo)), "r"(__float_as_uint(hi)));
    return r;
}
__device__ __forceinline__ void unpack2(ull v, float &lo, float &hi) {
    unsigned int a, b;
    asm("mov.b64 {%0, %1}, %2;" : "=r"(a), "=r"(b) : "l"(v));
    lo = __uint_as_float(a); hi = __uint_as_float(b);
}
// Packed fp32x2 FMA (sm_100+)
__device__ __forceinline__ ull fma2(ull a, ull b, ull c) {
    ull d; asm("fma.rn.f32x2 %0, %1, %2, %3;" : "=l"(d) : "l"(a), "l"(b), "l"(c)); return d;
}
__device__ __forceinline__ ull relu2(ull v) {
    float a, b; unpack2(v, a, b);
    return pack2(fmaxf(a, 0.f), fmaxf(b, 0.f));
}
// Vectorized no-return global reduction
__device__ __forceinline__ void red_add_v4(float* p, float a, float b, float c, float d) {
    asm volatile("red.global.add.v4.f32 [%0], {%1, %2, %3, %4};"
                 :: "l"(p), "f"(a), "f"(b), "f"(c), "f"(d) : "memory");
}

// ---------------------------------------------------------------------------
__global__ void zero_agg_kernel() {
    int i = blockIdx.x * blockDim.x + threadIdx.x;
    const int n4 = NN * HID / 4;
    float4* p = (float4*)g_agg;
    float4 z = make_float4(0.f, 0.f, 0.f, 0.f);
    for (; i < n4; i += gridDim.x * blockDim.x) p[i] = z;
}

// ---------------------------------------------------------------------------
// Edge kernel: PERSISTENT. 148 CTAs x 256 threads; each CTA loops over
// 128-edge tiles. Weights loaded to smem once, biases to regs once.
// Thread (tx=tid&15, ty=tid>>4) computes edges {4tx..4tx+3, 64+4tx..+3}
// x outputs {4ty..4ty+3}. Activation loads are 16B @ stride 16B -> 2
// wavefronts (minimum). Weight loads broadcast (2 distinct 16B/warp).
//
// Smem: W1d [129*64]f2 @0 (66048) | W2d [64*64]f2 @66048 (32768)
//       xT [129*128]f @98816 (66048, reused as oT) | h1T [64*128]f @164864 (32768)
#define E_W1D_OFF 0
#define E_W2D_OFF 66048
#define E_XT_OFF  98816
#define E_H1T_OFF 164864
#define E_SMEM    197632

__global__ __launch_bounds__(256, 1) void edge_kernel(
    const float* __restrict__ h, const float* __restrict__ coord,
    const int* __restrict__ row, const int* __restrict__ col,
    const float* __restrict__ edge_mask,
    const float* __restrict__ W1, const float* __restrict__ b1,
    const float* __restrict__ W2, const float* __restrict__ b2)
{
    extern __shared__ char smem[];
    float2* W1d = (float2*)(smem + E_W1D_OFF);
    float2* W2d = (float2*)(smem + E_W2D_OFF);
    float*  xT  = (float*)(smem + E_XT_OFF);
    float*  h1T = (float*)(smem + E_H1T_OFF);
    float*  oT  = xT;

    const int tid  = threadIdx.x;
    const int warp = tid >> 5, lane = tid & 31;
    const int tx = tid & 15, ty = tid >> 4;

    // One-time: weights duplicated for packed multipliers
    for (int i = tid; i < 129 * 64; i += 256) { float w = W1[i]; W1d[i] = make_float2(w, w); }
    for (int i = tid; i < 64 * 64;  i += 256) { float w = W2[i]; W2d[i] = make_float2(w, w); }
    // One-time: biases packed in registers
    ull bias1[4], bias2[4];
    #pragma unroll
    for (int j = 0; j < 4; j++) {
        float v1 = __ldg(b1 + 4 * ty + j); bias1[j] = pack2(v1, v1);
        float v2 = __ldg(b2 + 4 * ty + j); bias2[j] = pack2(v2, v2);
    }
    __syncthreads();

    for (int blk = blockIdx.x; blk < NTILES; blk += gridDim.x) {
        const int e0 = blk * 128;

        // --- Phase A: gather + register transpose into xT[k][e] ---
        {
            int4 r4 = ((const int4*)row)[blk * 32 + lane];
            int4 c4 = ((const int4*)col)[blk * 32 + lane];
            #pragma unroll
            for (int it = 0; it < 4; it++) {
                int ug = warp + it * 8;            // 0..31
                bool isrow = (ug < 16);
                int kk = isrow ? 4 * ug : 4 * (ug - 16);
                int kb = isrow ? 4 * ug : 64 + 4 * (ug - 16);
                int4 s = isrow ? r4 : c4;
                float4 f0 = *(const float4*)(h + (size_t)s.x * NF + kk);
                float4 f1 = *(const float4*)(h + (size_t)s.y * NF + kk);
                float4 f2 = *(const float4*)(h + (size_t)s.z * NF + kk);
                float4 f3 = *(const float4*)(h + (size_t)s.w * NF + kk);
                *(float4*)(xT + (kb + 0) * 128 + 4 * lane) = make_float4(f0.x, f1.x, f2.x, f3.x);
                *(float4*)(xT + (kb + 1) * 128 + 4 * lane) = make_float4(f0.y, f1.y, f2.y, f3.y);
                *(float4*)(xT + (kb + 2) * 128 + 4 * lane) = make_float4(f0.z, f1.z, f2.z, f3.z);
                *(float4*)(xT + (kb + 3) * 128 + 4 * lane) = make_float4(f0.w, f1.w, f2.w, f3.w);
            }
        }
        if (tid < 128) {   // radial row k=128
            int e = e0 + tid;
            int r = row[e], c = col[e];
            float dx = coord[3 * r]     - coord[3 * c];
            float dy = coord[3 * r + 1] - coord[3 * c + 1];
            float dz = coord[3 * r + 2] - coord[3 * c + 2];
            xT[128 * 128 + tid] = dx * dx + dy * dy + dz * dz;
        }
        __syncthreads();

        ull acc[4][4];

        // --- GEMM1 (K=129), relu ---
        #pragma unroll
        for (int j = 0; j < 4; j++)
            #pragma unroll
            for (int i = 0; i < 4; i++) acc[i][j] = bias1[j];
        #pragma unroll 3
        for (int k = 0; k < 129; k++) {
            ulonglong2 aA = *(const ulonglong2*)(xT + k * 128 + 4 * tx);        // edges 4tx..+3
            ulonglong2 aB = *(const ulonglong2*)(xT + k * 128 + 64 + 4 * tx);   // edges 64+4tx..+3
            ulonglong2 w01 = *(const ulonglong2*)(W1d + k * 64 + 4 * ty);
            ulonglong2 w23 = *(const ulonglong2*)(W1d + k * 64 + 4 * ty + 2);
            ull a[4] = {aA.x, aA.y, aB.x, aB.y};
            ull w[4] = {w01.x, w01.y, w23.x, w23.y};
            #pragma unroll
            for (int i = 0; i < 4; i++)
                #pragma unroll
                for (int j = 0; j < 4; j++)
                    acc[i][j] = fma2(a[i], w[j], acc[i][j]);
        }
        #pragma unroll
        for (int j = 0; j < 4; j++) {
            ulonglong2 vA; vA.x = relu2(acc[0][j]); vA.y = relu2(acc[1][j]);
            ulonglong2 vB; vB.x = relu2(acc[2][j]); vB.y = relu2(acc[3][j]);
            *(ulonglong2*)(h1T + (4 * ty + j) * 128 + 4 * tx)      = vA;
            *(ulonglong2*)(h1T + (4 * ty + j) * 128 + 64 + 4 * tx) = vB;
        }
        __syncthreads();

        // --- GEMM2 (K=64), relu ---
        #pragma unroll
        for (int j = 0; j < 4; j++)
            #pragma unroll
            for (int i = 0; i < 4; i++) acc[i][j] = bias2[j];
        #pragma unroll 4
        for (int k = 0; k < 64; k++) {
            ulonglong2 aA = *(const ulonglong2*)(h1T + k * 128 + 4 * tx);
            ulonglong2 aB = *(const ulonglong2*)(h1T + k * 128 + 64 + 4 * tx);
            ulonglong2 w01 = *(const ulonglong2*)(W2d + k * 64 + 4 * ty);
            ulonglong2 w23 = *(const ulonglong2*)(W2d + k * 64 + 4 * ty + 2);
            ull a[4] = {aA.x, aA.y, aB.x, aB.y};
            ull w[4] = {w01.x, w01.y, w23.x, w23.y};
            #pragma unroll
            for (int i = 0; i < 4; i++)
                #pragma unroll
                for (int j = 0; j < 4; j++)
                    acc[i][j] = fma2(a[i], w[j], acc[i][j]);
        }
        #pragma unroll
        for (int j = 0; j < 4; j++) {
            ulonglong2 vA; vA.x = relu2(acc[0][j]); vA.y = relu2(acc[1][j]);
            ulonglong2 vB; vB.x = relu2(acc[2][j]); vB.y = relu2(acc[3][j]);
            *(ulonglong2*)(oT + (4 * ty + j) * 128 + 4 * tx)      = vA;
            *(ulonglong2*)(oT + (4 * ty + j) * 128 + 64 + 4 * tx) = vB;
        }
        __syncthreads();

        // --- Phase D: mask + scatter-add (2 threads/edge, 32 feats each) ---
        {
            int e_l = tid >> 1, half = tid & 1;
            int e = e0 + e_l;
            int r = row[e];
            float em = edge_mask[e];
            float* dst = g_agg + (size_t)r * HID + half * 32;
            const float* src = oT + (half * 32) * 128 + e_l;
            #pragma unroll
            for (int jj = 0; jj < 32; jj += 4) {
                red_add_v4(dst + jj,
                           src[(jj    ) * 128] * em,
                           src[(jj + 1) * 128] * em,
                           src[(jj + 2) * 128] * em,
                           src[(jj + 3) * 128] * em);
            }
        }
        __syncthreads();   // oT (=xT) consumed before next tile's Phase A
    }
}

// ---------------------------------------------------------------------------
// Node kernel: same skeleton, non-persistent (391 blocks).
#define N_W1D_OFF 0
#define N_W2D_OFF 65536
#define N_XT_OFF  98304
#define N_H1T_OFF 163840
#define N_SMEM    196608

__global__ __launch_bounds__(256, 1) void node_kernel(
    const float* __restrict__ h,
    const float* __restrict__ W1, const float* __restrict__ b1,
    const float* __restrict__ W2, const float* __restrict__ b2,
    float* __restrict__ hout)
{
    extern __shared__ char smem[];
    float2* W1d = (float2*)(smem + N_W1D_OFF);
    float2* W2d = (float2*)(smem + N_W2D_OFF);
    float*  xT  = (float*)(smem + N_XT_OFF);
    float*  h1T = (float*)(smem + N_H1T_OFF);
    float*  oT  = xT;

    const int tid  = threadIdx.x;
    const int warp = tid >> 5, lane = tid & 31;
    const int tx = tid & 15, ty = tid >> 4;
    const int n0 = blockIdx.x * 128;

    for (int i = tid; i < 128 * 64; i += 256) { float w = W1[i]; W1d[i] = make_float2(w, w); }
    for (int i = tid; i < 64 * 64;  i += 256) { float w = W2[i]; W2d[i] = make_float2(w, w); }
    ull bias1[4], bias2[4];
    #pragma unroll
    for (int j = 0; j < 4; j++) {
        float v1 = __ldg(b1 + 4 * ty + j); bias1[j] = pack2(v1, v1);
        float v2 = __ldg(b2 + 4 * ty + j); bias2[j] = pack2(v2, v2);
    }

    // Phase A: stage [h || agg] transposed (clamped for tail block)
    {
        #pragma unroll
        for (int it = 0; it < 4; it++) {
            int ug = warp + it * 8;
            bool isH = (ug < 16);
            int kk = isH ? 4 * ug : 4 * (ug - 16);
            int kb = isH ? 4 * ug : 64 + 4 * (ug - 16);
            const float* src = isH ? h : g_agg;
            int na = min(n0 + 4 * lane + 0, NN - 1);
            int nb = min(n0 + 4 * lane + 1, NN - 1);
            int nc = min(n0 + 4 * lane + 2, NN - 1);
            int nd = min(n0 + 4 * lane + 3, NN - 1);
            float4 f0 = *(const float4*)(src + (size_t)na * 64 + kk);
            float4 f1 = *(const float4*)(src + (size_t)nb * 64 + kk);
            float4 f2 = *(const float4*)(src + (size_t)nc * 64 + kk);
            float4 f3 = *(const float4*)(src + (size_t)nd * 64 + kk);
            *(float4*)(xT + (kb + 0) * 128 + 4 * lane) = make_float4(f0.x, f1.x, f2.x, f3.x);
            *(float4*)(xT + (kb + 1) * 128 + 4 * lane) = make_float4(f0.y, f1.y, f2.y, f3.y);
            *(float4*)(xT + (kb + 2) * 128 + 4 * lane) = make_float4(f0.z, f1.z, f2.z, f3.z);
            *(float4*)(xT + (kb + 3) * 128 + 4 * lane) = make_float4(f0.w, f1.w, f2.w, f3.w);
        }
    }
    __syncthreads();

    ull acc[4][4];

    // GEMM1 K=128, relu
    #pragma unroll
    for (int j = 0; j < 4; j++)
        #pragma unroll
        for (int i = 0; i < 4; i++) acc[i][j] = bias1[j];
    #pragma unroll 4
    for (int k = 0; k < 128; k++) {
        ulonglong2 aA = *(const ulonglong2*)(xT + k * 128 + 4 * tx);
        ulonglong2 aB = *(const ulonglong2*)(xT + k * 128 + 64 + 4 * tx);
        ulonglong2 w01 = *(const ulonglong2*)(W1d + k * 64 + 4 * ty);
        ulonglong2 w23 = *(const ulonglong2*)(W1d + k * 64 + 4 * ty + 2);
        ull a[4] = {aA.x, aA.y, aB.x, aB.y};
        ull w[4] = {w01.x, w01.y, w23.x, w23.y};
        #pragma unroll
        for (int i = 0; i < 4; i++)
            #pragma unroll
            for (int j = 0; j < 4; j++)
                acc[i][j] = fma2(a[i], w[j], acc[i][j]);
    }
    #pragma unroll
    for (int j = 0; j < 4; j++) {
        ulonglong2 vA; vA.x = relu2(acc[0][j]); vA.y = relu2(acc[1][j]);
        ulonglong2 vB; vB.x = relu2(acc[2][j]); vB.y = relu2(acc[3][j]);
        *(ulonglong2*)(h1T + (4 * ty + j) * 128 + 4 * tx)      = vA;
        *(ulonglong2*)(h1T + (4 * ty + j) * 128 + 64 + 4 * tx) = vB;
    }
    __syncthreads();

    // GEMM2 K=64 (no relu)
    #pragma unroll
    for (int j = 0; j < 4; j++)
        #pragma unroll
        for (int i = 0; i < 4; i++) acc[i][j] = bias2[j];
    #pragma unroll 4
    for (int k = 0; k < 64; k++) {
        ulonglong2 aA = *(const ulonglong2*)(h1T + k * 128 + 4 * tx);
        ulonglong2 aB = *(const ulonglong2*)(h1T + k * 128 + 64 + 4 * tx);
        ulonglong2 w01 = *(const ulonglong2*)(W2d + k * 64 + 4 * ty);
        ulonglong2 w23 = *(const ulonglong2*)(W2d + k * 64 + 4 * ty + 2);
        ull a[4] = {aA.x, aA.y, aB.x, aB.y};
        ull w[4] = {w01.x, w01.y, w23.x, w23.y};
        #pragma unroll
        for (int i = 0; i < 4; i++)
            #pragma unroll
            for (int j = 0; j < 4; j++)
                acc[i][j] = fma2(a[i], w[j], acc[i][j]);
    }
    #pragma unroll
    for (int j = 0; j < 4; j++) {
        ulonglong2 vA; vA.x = acc[0][j]; vA.y = acc[1][j];
        ulonglong2 vB; vB.x = acc[2][j]; vB.y = acc[3][j];
        *(ulonglong2*)(oT + (4 * ty + j) * 128 + 4 * tx)      = vA;
        *(ulonglong2*)(oT + (4 * ty + j) * 128 + 64 + 4 * tx) = vB;
    }
    __syncthreads();

    // Residual + coalesced stores
    {
        int n_l = tid >> 1, half = tid & 1;
        int n = n0 + n_l;
        if (n < NN) {
            const float* hr = h + (size_t)n * NF + half * 32;
            float* orow = hout + (size_t)n * NF + half * 32;
            const float* src = oT + (half * 32) * 128 + n_l;
            #pragma unroll
            for (int jj = 0; jj < 32; jj += 4) {
                float4 hv = *(const float4*)(hr + jj);
                float4 o;
                o.x = src[(jj    ) * 128] + hv.x;
                o.y = src[(jj + 1) * 128] + hv.y;
                o.z = src[(jj + 2) * 128] + hv.z;
                o.w = src[(jj + 3) * 128] + hv.w;
                *(float4*)(orow + jj) = o;
            }
        }
    }
}

// ---------------------------------------------------------------------------
extern "C" void kernel_launch(void* const* d_in, const int* in_sizes, int n_in,
                              void* d_out, int out_size) {
    const float* h         = (const float*)d_in[0];
    const float* coord     = (const float*)d_in[1];
    const int*   row       = (const int*)d_in[2];
    const int*   col       = (const int*)d_in[3];
    // d_in[4] = node_mask (unused on the reference path)
    const float* edge_mask = (const float*)d_in[5];
    const float* W_e1 = (const float*)d_in[6];
    const float* b_e1 = (const float*)d_in[7];
    const float* W_e2 = (const float*)d_in[8];
    const float* b_e2 = (const float*)d_in[9];
    const float* W_n1 = (const float*)d_in[10];
    const float* b_n1 = (const float*)d_in[11];
    const float* W_n2 = (const float*)d_in[12];
    const float* b_n2 = (const float*)d_in[13];
    float* out = (float*)d_out;

    cudaFuncSetAttribute(edge_kernel, cudaFuncAttributeMaxDynamicSharedMemorySize, E_SMEM);
    cudaFuncSetAttribute(node_kernel, cudaFuncAttributeMaxDynamicSharedMemorySize, N_SMEM);

    zero_agg_kernel<<<512, 256>>>();
    edge_kernel<<<148, 256, E_SMEM>>>(h, coord, row, col, edge_mask,
                                      W_e1, b_e1, W_e2, b_e2);
    node_kernel<<<(NN + 127) / 128, 256, N_SMEM>>>(h, W_n1, b_n1, W_n2, b_n2, out);
    cudaMemcpyAsync(out + (size_t)NN * NF, coord, (size_t)NN * 3 * sizeof(float),
                    cudaMemcpyDeviceToDevice, 0);
}

// round 7
// speedup vs baseline: 1.6506x; 1.0346x over previous
#include <cuda_runtime.h>
#include <cstdint>
#include <cstddef>

#define NN 50000
#define EE 800000
#define NF 64
#define HID 64
#define NTILES (EE / 128)

// Scatter-sum accumulator (allocation-free scratch: device global)
__device__ float g_agg[NN * HID];

typedef unsigned long long ull;

__device__ __forceinline__ ull pack2(float lo, float hi) {
    ull r;
    asm("mov.b64 %0, {%1, %2};" : "=l"(r) : "r"(__float_as_uint(lo)), "r"(__float_as_uint(hi)));
    return r;
}
__device__ __forceinline__ void unpack2(ull v, float &lo, float &hi) {
    unsigned int a, b;
    asm("mov.b64 {%0, %1}, %2;" : "=r"(a), "=r"(b) : "l"(v));
    lo = __uint_as_float(a); hi = __uint_as_float(b);
}
// Packed fp32x2 FMA (sm_100+)
__device__ __forceinline__ ull fma2(ull a, ull b, ull c) {
    ull d; asm("fma.rn.f32x2 %0, %1, %2, %3;" : "=l"(d) : "l"(a), "l"(b), "l"(c)); return d;
}
__device__ __forceinline__ ull relu2(ull v) {
    float a, b; unpack2(v, a, b);
    return pack2(fmaxf(a, 0.f), fmaxf(b, 0.f));
}
// Vectorized no-return global reduction
__device__ __forceinline__ void red_add_v4(float* p, float a, float b, float c, float d) {
    asm volatile("red.global.add.v4.f32 [%0], {%1, %2, %3, %4};"
                 :: "l"(p), "f"(a), "f"(b), "f"(c), "f"(d) : "memory");
}

// ---------------------------------------------------------------------------
__global__ void zero_agg_kernel() {
    int i = blockIdx.x * blockDim.x + threadIdx.x;
    const int n4 = NN * HID / 4;
    float4* p = (float4*)g_agg;
    float4 z = make_float4(0.f, 0.f, 0.f, 0.f);
    for (; i < n4; i += gridDim.x * blockDim.x) p[i] = z;
}

// ---------------------------------------------------------------------------
// Edge kernel: PERSISTENT + SOFTWARE-PIPELINED.
// 148 CTAs x 256 threads; each CTA loops over 128-edge tiles.
// Per tile: STS stage (from prefetched regs) -> GEMM1 -> GEMM2 -> scatter,
// with the NEXT tile's gather LDGs issued before GEMM1 so their latency
// and L1tex wavefront time overlap the ~18K-cycle FMA phase.
//
// Smem: W1d [129*64]f2 @0 (66048) | W2d [64*64]f2 @66048 (32768)
//       xT [129*128]f @98816 (66048, reused as oT) | h1T [64*128]f @164864 (32768)
#define E_W1D_OFF 0
#define E_W2D_OFF 66048
#define E_XT_OFF  98816
#define E_H1T_OFF 164864
#define E_SMEM    197632

__global__ __launch_bounds__(256, 1) void edge_kernel(
    const float* __restrict__ h, const float* __restrict__ coord,
    const int* __restrict__ row, const int* __restrict__ col,
    const float* __restrict__ edge_mask,
    const float* __restrict__ W1, const float* __restrict__ b1,
    const float* __restrict__ W2, const float* __restrict__ b2)
{
    extern __shared__ char smem[];
    float2* W1d = (float2*)(smem + E_W1D_OFF);
    float2* W2d = (float2*)(smem + E_W2D_OFF);
    float*  xT  = (float*)(smem + E_XT_OFF);
    float*  h1T = (float*)(smem + E_H1T_OFF);
    float*  oT  = xT;

    const int tid  = threadIdx.x;
    const int warp = tid >> 5, lane = tid & 31;
    const int tx = tid & 15, ty = tid >> 4;
    const int stride = gridDim.x;

    // One-time: weights duplicated for packed multipliers
    for (int i = tid; i < 129 * 64; i += 256) { float w = W1[i]; W1d[i] = make_float2(w, w); }
    for (int i = tid; i < 64 * 64;  i += 256) { float w = W2[i]; W2d[i] = make_float2(w, w); }
    // One-time: biases packed in registers
    ull bias1[4], bias2[4];
    #pragma unroll
    for (int j = 0; j < 4; j++) {
        float v1 = __ldg(b1 + 4 * ty + j); bias1[j] = pack2(v1, v1);
        float v2 = __ldg(b2 + 4 * ty + j); bias2[j] = pack2(v2, v2);
    }
    __syncthreads();

    // ---- prefetch registers ----
    int4 r4, c4;
    float4 g[4][4];                 // [it][quad-member]
    float crx, cry, crz, ccx, ccy, ccz;

    // Prefetch tile 'pb' into registers
    #define PREFETCH_TILE(pb)                                                   \
    {                                                                           \
        r4 = ((const int4*)row)[(pb) * 32 + lane];                              \
        c4 = ((const int4*)col)[(pb) * 32 + lane];                              \
        _Pragma("unroll")                                                       \
        for (int it = 0; it < 4; it++) {                                        \
            int ug = warp + it * 8;                                             \
            bool isrow = (ug < 16);                                             \
            int kk = isrow ? 4 * ug : 4 * (ug - 16);                            \
            int4 s = isrow ? r4 : c4;                                           \
            g[it][0] = *(const float4*)(h + (size_t)s.x * NF + kk);             \
            g[it][1] = *(const float4*)(h + (size_t)s.y * NF + kk);             \
            g[it][2] = *(const float4*)(h + (size_t)s.z * NF + kk);             \
            g[it][3] = *(const float4*)(h + (size_t)s.w * NF + kk);             \
        }                                                                       \
        if (tid < 128) {                                                        \
            int e = (pb) * 128 + tid;                                           \
            int rr = row[e], cc = col[e];                                       \
            crx = coord[3 * rr];     ccx = coord[3 * cc];                       \
            cry = coord[3 * rr + 1]; ccy = coord[3 * cc + 1];                   \
            crz = coord[3 * rr + 2]; ccz = coord[3 * cc + 2];                   \
        }                                                                       \
    }

    int blk = blockIdx.x;
    PREFETCH_TILE(blk);

    for (; blk < NTILES; blk += stride) {
        const int e0 = blk * 128;

        // --- STS stage: write prefetched tile into xT (register transpose) ---
        #pragma unroll
        for (int it = 0; it < 4; it++) {
            int ug = warp + it * 8;
            bool isrow = (ug < 16);
            int kb = isrow ? 4 * ug : 64 + 4 * (ug - 16);
            float4 f0 = g[it][0], f1 = g[it][1], f2 = g[it][2], f3 = g[it][3];
            *(float4*)(xT + (kb + 0) * 128 + 4 * lane) = make_float4(f0.x, f1.x, f2.x, f3.x);
            *(float4*)(xT + (kb + 1) * 128 + 4 * lane) = make_float4(f0.y, f1.y, f2.y, f3.y);
            *(float4*)(xT + (kb + 2) * 128 + 4 * lane) = make_float4(f0.z, f1.z, f2.z, f3.z);
            *(float4*)(xT + (kb + 3) * 128 + 4 * lane) = make_float4(f0.w, f1.w, f2.w, f3.w);
        }
        if (tid < 128) {   // radial row k=128 (from prefetched coords)
            float dx = crx - ccx, dy = cry - ccy, dz = crz - ccz;
            xT[128 * 128 + tid] = dx * dx + dy * dy + dz * dz;
        }
        __syncthreads();

        // --- prefetch NEXT tile + current tile's scatter metadata ---
        float em_c = edge_mask[e0 + (tid >> 1)];
        int   r_c  = row[e0 + (tid >> 1)];
        {
            int nblk = blk + stride;
            int pblk = (nblk < NTILES) ? nblk : blk;   // clamp: harmless reload
            PREFETCH_TILE(pblk);
        }

        ull acc[4][4];

        // --- GEMM1 (K=129), relu ---
        #pragma unroll
        for (int j = 0; j < 4; j++)
            #pragma unroll
            for (int i = 0; i < 4; i++) acc[i][j] = bias1[j];
        #pragma unroll 3
        for (int k = 0; k < 129; k++) {
            ulonglong2 aA = *(const ulonglong2*)(xT + k * 128 + 4 * tx);
            ulonglong2 aB = *(const ulonglong2*)(xT + k * 128 + 64 + 4 * tx);
            ulonglong2 w01 = *(const ulonglong2*)(W1d + k * 64 + 4 * ty);
            ulonglong2 w23 = *(const ulonglong2*)(W1d + k * 64 + 4 * ty + 2);
            ull a[4] = {aA.x, aA.y, aB.x, aB.y};
            ull w[4] = {w01.x, w01.y, w23.x, w23.y};
            #pragma unroll
            for (int i = 0; i < 4; i++)
                #pragma unroll
                for (int j = 0; j < 4; j++)
                    acc[i][j] = fma2(a[i], w[j], acc[i][j]);
        }
        #pragma unroll
        for (int j = 0; j < 4; j++) {
            ulonglong2 vA; vA.x = relu2(acc[0][j]); vA.y = relu2(acc[1][j]);
            ulonglong2 vB; vB.x = relu2(acc[2][j]); vB.y = relu2(acc[3][j]);
            *(ulonglong2*)(h1T + (4 * ty + j) * 128 + 4 * tx)      = vA;
            *(ulonglong2*)(h1T + (4 * ty + j) * 128 + 64 + 4 * tx) = vB;
        }
        __syncthreads();

        // --- GEMM2 (K=64), relu ---
        #pragma unroll
        for (int j = 0; j < 4; j++)
            #pragma unroll
            for (int i = 0; i < 4; i++) acc[i][j] = bias2[j];
        #pragma unroll 4
        for (int k = 0; k < 64; k++) {
            ulonglong2 aA = *(const ulonglong2*)(h1T + k * 128 + 4 * tx);
            ulonglong2 aB = *(const ulonglong2*)(h1T + k * 128 + 64 + 4 * tx);
            ulonglong2 w01 = *(const ulonglong2*)(W2d + k * 64 + 4 * ty);
            ulonglong2 w23 = *(const ulonglong2*)(W2d + k * 64 + 4 * ty + 2);
            ull a[4] = {aA.x, aA.y, aB.x, aB.y};
            ull w[4] = {w01.x, w01.y, w23.x, w23.y};
            #pragma unroll
            for (int i = 0; i < 4; i++)
                #pragma unroll
                for (int j = 0; j < 4; j++)
                    acc[i][j] = fma2(a[i], w[j], acc[i][j]);
        }
        #pragma unroll
        for (int j = 0; j < 4; j++) {
            ulonglong2 vA; vA.x = relu2(acc[0][j]); vA.y = relu2(acc[1][j]);
            ulonglong2 vB; vB.x = relu2(acc[2][j]); vB.y = relu2(acc[3][j]);
            *(ulonglong2*)(oT + (4 * ty + j) * 128 + 4 * tx)      = vA;
            *(ulonglong2*)(oT + (4 * ty + j) * 128 + 64 + 4 * tx) = vB;
        }
        __syncthreads();

        // --- Phase D: mask + scatter-add (2 threads/edge, 32 feats each) ---
        {
            int e_l = tid >> 1, half = tid & 1;
            float* dst = g_agg + (size_t)r_c * HID + half * 32;
            const float* src = oT + (half * 32) * 128 + e_l;
            #pragma unroll
            for (int jj = 0; jj < 32; jj += 4) {
                red_add_v4(dst + jj,
                           src[(jj    ) * 128] * em_c,
                           src[(jj + 1) * 128] * em_c,
                           src[(jj + 2) * 128] * em_c,
                           src[(jj + 3) * 128] * em_c);
            }
        }
        __syncthreads();   // oT (=xT) consumed before next tile's STS stage
    }
    #undef PREFETCH_TILE
}

// ---------------------------------------------------------------------------
// Node kernel: non-persistent (391 blocks). Same GEMM skeleton.
#define N_W1D_OFF 0
#define N_W2D_OFF 65536
#define N_XT_OFF  98304
#define N_H1T_OFF 163840
#define N_SMEM    196608

__global__ __launch_bounds__(256, 1) void node_kernel(
    const float* __restrict__ h,
    const float* __restrict__ W1, const float* __restrict__ b1,
    const float* __restrict__ W2, const float* __restrict__ b2,
    float* __restrict__ hout)
{
    extern __shared__ char smem[];
    float2* W1d = (float2*)(smem + N_W1D_OFF);
    float2* W2d = (float2*)(smem + N_W2D_OFF);
    float*  xT  = (float*)(smem + N_XT_OFF);
    float*  h1T = (float*)(smem + N_H1T_OFF);
    float*  oT  = xT;

    const int tid  = threadIdx.x;
    const int warp = tid >> 5, lane = tid & 31;
    const int tx = tid & 15, ty = tid >> 4;
    const int n0 = blockIdx.x * 128;

    for (int i = tid; i < 128 * 64; i += 256) { float w = W1[i]; W1d[i] = make_float2(w, w); }
    for (int i = tid; i < 64 * 64;  i += 256) { float w = W2[i]; W2d[i] = make_float2(w, w); }
    ull bias1[4], bias2[4];
    #pragma unroll
    for (int j = 0; j < 4; j++) {
        float v1 = __ldg(b1 + 4 * ty + j); bias1[j] = pack2(v1, v1);
        float v2 = __ldg(b2 + 4 * ty + j); bias2[j] = pack2(v2, v2);
    }

    // Phase A: stage [h || agg] transposed (clamped for tail block)
    {
        #pragma unroll
        for (int it = 0; it < 4; it++) {
            int ug = warp + it * 8;
            bool isH = (ug < 16);
            int kk = isH ? 4 * ug : 4 * (ug - 16);
            int kb = isH ? 4 * ug : 64 + 4 * (ug - 16);
            const float* src = isH ? h : g_agg;
            int na = min(n0 + 4 * lane + 0, NN - 1);
            int nb = min(n0 + 4 * lane + 1, NN - 1);
            int nc = min(n0 + 4 * lane + 2, NN - 1);
            int nd = min(n0 + 4 * lane + 3, NN - 1);
            float4 f0 = *(const float4*)(src + (size_t)na * 64 + kk);
            float4 f1 = *(const float4*)(src + (size_t)nb * 64 + kk);
            float4 f2 = *(const float4*)(src + (size_t)nc * 64 + kk);
            float4 f3 = *(const float4*)(src + (size_t)nd * 64 + kk);
            *(float4*)(xT + (kb + 0) * 128 + 4 * lane) = make_float4(f0.x, f1.x, f2.x, f3.x);
            *(float4*)(xT + (kb + 1) * 128 + 4 * lane) = make_float4(f0.y, f1.y, f2.y, f3.y);
            *(float4*)(xT + (kb + 2) * 128 + 4 * lane) = make_float4(f0.z, f1.z, f2.z, f3.z);
            *(float4*)(xT + (kb + 3) * 128 + 4 * lane) = make_float4(f0.w, f1.w, f2.w, f3.w);
        }
    }
    __syncthreads();

    ull acc[4][4];

    // GEMM1 K=128, relu
    #pragma unroll
    for (int j = 0; j < 4; j++)
        #pragma unroll
        for (int i = 0; i < 4; i++) acc[i][j] = bias1[j];
    #pragma unroll 4
    for (int k = 0; k < 128; k++) {
        ulonglong2 aA = *(const ulonglong2*)(xT + k * 128 + 4 * tx);
        ulonglong2 aB = *(const ulonglong2*)(xT + k * 128 + 64 + 4 * tx);
        ulonglong2 w01 = *(const ulonglong2*)(W1d + k * 64 + 4 * ty);
        ulonglong2 w23 = *(const ulonglong2*)(W1d + k * 64 + 4 * ty + 2);
        ull a[4] = {aA.x, aA.y, aB.x, aB.y};
        ull w[4] = {w01.x, w01.y, w23.x, w23.y};
        #pragma unroll
        for (int i = 0; i < 4; i++)
            #pragma unroll
            for (int j = 0; j < 4; j++)
                acc[i][j] = fma2(a[i], w[j], acc[i][j]);
    }
    #pragma unroll
    for (int j = 0; j < 4; j++) {
        ulonglong2 vA; vA.x = relu2(acc[0][j]); vA.y = relu2(acc[1][j]);
        ulonglong2 vB; vB.x = relu2(acc[2][j]); vB.y = relu2(acc[3][j]);
        *(ulonglong2*)(h1T + (4 * ty + j) * 128 + 4 * tx)      = vA;
        *(ulonglong2*)(h1T + (4 * ty + j) * 128 + 64 + 4 * tx) = vB;
    }
    __syncthreads();

    // GEMM2 K=64 (no relu)
    #pragma unroll
    for (int j = 0; j < 4; j++)
        #pragma unroll
        for (int i = 0; i < 4; i++) acc[i][j] = bias2[j];
    #pragma unroll 4
    for (int k = 0; k < 64; k++) {
        ulonglong2 aA = *(const ulonglong2*)(h1T + k * 128 + 4 * tx);
        ulonglong2 aB = *(const ulonglong2*)(h1T + k * 128 + 64 + 4 * tx);
        ulonglong2 w01 = *(const ulonglong2*)(W2d + k * 64 + 4 * ty);
        ulonglong2 w23 = *(const ulonglong2*)(W2d + k * 64 + 4 * ty + 2);
        ull a[4] = {aA.x, aA.y, aB.x, aB.y};
        ull w[4] = {w01.x, w01.y, w23.x, w23.y};
        #pragma unroll
        for (int i = 0; i < 4; i++)
            #pragma unroll
            for (int j = 0; j < 4; j++)
                acc[i][j] = fma2(a[i], w[j], acc[i][j]);
    }
    #pragma unroll
    for (int j = 0; j < 4; j++) {
        ulonglong2 vA; vA.x = acc[0][j]; vA.y = acc[1][j];
        ulonglong2 vB; vB.x = acc[2][j]; vB.y = acc[3][j];
        *(ulonglong2*)(oT + (4 * ty + j) * 128 + 4 * tx)      = vA;
        *(ulonglong2*)(oT + (4 * ty + j) * 128 + 64 + 4 * tx) = vB;
    }
    __syncthreads();

    // Residual + coalesced stores
    {
        int n_l = tid >> 1, half = tid & 1;
        int n = n0 + n_l;
        if (n < NN) {
            const float* hr = h + (size_t)n * NF + half * 32;
            float* orow = hout + (size_t)n * NF + half * 32;
            const float* src = oT + (half * 32) * 128 + n_l;
            #pragma unroll
            for (int jj = 0; jj < 32; jj += 4) {
                float4 hv = *(const float4*)(hr + jj);
                float4 o;
                o.x = src[(jj    ) * 128] + hv.x;
                o.y = src[(jj + 1) * 128] + hv.y;
                o.z = src[(jj + 2) * 128] + hv.z;
                o.w = src[(jj + 3) * 128] + hv.w;
                *(float4*)(orow + jj) = o;
            }
        }
    }
}

// ---------------------------------------------------------------------------
// Coord passthrough as a KERNEL (not memcpy) so the per-replay kernel count
// is 4 and edge_kernel lands on ncu's captured launch (-s 5 -c 1 => #6).
__global__ void copy_coord_kernel(const float* __restrict__ coord,
                                  float* __restrict__ dst) {
    int i = blockIdx.x * blockDim.x + threadIdx.x;
    const int n4 = NN * 3 / 4;   // 37500 exact
    if (i < n4) ((float4*)dst)[i] = ((const float4*)coord)[i];
}

// ---------------------------------------------------------------------------
extern "C" void kernel_launch(void* const* d_in, const int* in_sizes, int n_in,
                              void* d_out, int out_size) {
    const float* h         = (const float*)d_in[0];
    const float* coord     = (const float*)d_in[1];
    const int*   row       = (const int*)d_in[2];
    const int*   col       = (const int*)d_in[3];
    // d_in[4] = node_mask (unused on the reference path)
    const float* edge_mask = (const float*)d_in[5];
    const float* W_e1 = (const float*)d_in[6];
    const float* b_e1 = (const float*)d_in[7];
    const float* W_e2 = (const float*)d_in[8];
    const float* b_e2 = (const float*)d_in[9];
    const float* W_n1 = (const float*)d_in[10];
    const float* b_n1 = (const float*)d_in[11];
    const float* W_n2 = (const float*)d_in[12];
    const float* b_n2 = (const float*)d_in[13];
    float* out = (float*)d_out;

    cudaFuncSetAttribute(edge_kernel, cudaFuncAttributeMaxDynamicSharedMemorySize, E_SMEM);
    cudaFuncSetAttribute(node_kernel, cudaFuncAttributeMaxDynamicSharedMemorySize, N_SMEM);

    zero_agg_kernel<<<512, 256>>>();
    edge_kernel<<<148, 256, E_SMEM>>>(h, coord, row, col, edge_mask,
                                      W_e1, b_e1, W_e2, b_e2);
    node_kernel<<<(NN + 127) / 128, 256, N_SMEM>>>(h, W_n1, b_n1, W_n2, b_n2, out);
    copy_coord_kernel<<<(NN * 3 / 4 + 255) / 256, 256>>>(coord, out + (size_t)NN * NF);
}

// round 10
// speedup vs baseline: 3.6600x; 2.2174x over previous
#include <cuda_runtime.h>
#include <cstdint>
#include <cstddef>

#define NN 50000
#define EE 800000
#define NF 64
#define HID 64
#define TILE_E 256
#define NTILES (EE / TILE_E)   // 3125 exactly

// Scatter-sum accumulator (allocation-free scratch)
__device__ float g_agg[NN * HID];

typedef unsigned long long ull;

// ===== helpers =====
__device__ __forceinline__ uint32_t cvt_tf32(float f) {
    uint32_t r; asm("cvt.rna.tf32.f32 %0, %1;" : "=r"(r) : "f"(f)); return r;
}
__device__ __forceinline__ void red_add_v2(float* p, float a, float b) {
    asm volatile("red.global.add.v2.f32 [%0], {%1, %2};" :: "l"(p), "f"(a), "f"(b) : "memory");
}
// m16n8k8 tf32 MMA, D += A*B (C==D in-place)
#define MMA_TF32(c, a, b0, b1)                                                  \
    asm volatile("mma.sync.aligned.m16n8k8.row.col.f32.tf32.tf32.f32 "          \
        "{%0,%1,%2,%3}, {%4,%5,%6,%7}, {%8,%9}, {%0,%1,%2,%3};"                 \
        : "+f"((c)[0]), "+f"((c)[1]), "+f"((c)[2]), "+f"((c)[3])                \
        : "r"((a)[0]), "r"((a)[1]), "r"((a)[2]), "r"((a)[3]), "r"(b0), "r"(b1))

// fp32x2 helpers for the node kernel (kept from passing R7)
__device__ __forceinline__ ull pack2(float lo, float hi) {
    ull r;
    asm("mov.b64 %0, {%1, %2};" : "=l"(r) : "r"(__float_as_uint(lo)), "r"(__float_as_uint(hi)));
    return r;
}
__device__ __forceinline__ void unpack2(ull v, float &lo, float &hi) {
    unsigned int a, b;
    asm("mov.b64 {%0, %1}, %2;" : "=r"(a), "=r"(b) : "l"(v));
    lo = __uint_as_float(a); hi = __uint_as_float(b);
}
__device__ __forceinline__ ull fma2(ull a, ull b, ull c) {
    ull d; asm("fma.rn.f32x2 %0, %1, %2, %3;" : "=l"(d) : "l"(a), "l"(b), "l"(c)); return d;
}
__device__ __forceinline__ ull relu2(ull v) {
    float a, b; unpack2(v, a, b);
    return pack2(fmaxf(a, 0.f), fmaxf(b, 0.f));
}
__device__ __forceinline__ void red_add_v4(float* p, float a, float b, float c, float d) {
    asm volatile("red.global.add.v4.f32 [%0], {%1, %2, %3, %4};"
                 :: "l"(p), "f"(a), "f"(b), "f"(c), "f"(d) : "memory");
}

// ---------------------------------------------------------------------------
__global__ void zero_agg_kernel() {
    int i = blockIdx.x * blockDim.x + threadIdx.x;
    const int n4 = NN * HID / 4;
    float4* p = (float4*)g_agg;
    float4 z = make_float4(0.f, 0.f, 0.f, 0.f);
    for (; i < n4; i += gridDim.x * blockDim.x) p[i] = z;
}

// ---------------------------------------------------------------------------
// Edge kernel: persistent, tf32 mma.sync (sm_80 ISA -> HMMA on sm_100).
// Tile = 256 edges. 8 warps, warp tile 32 edges x 64 outputs.
// Strides: xS/W1t = 132 floats, h1/W2t = 68 floats (both ≡4 mod 32 ->
// all fragment LDS.32 accesses are bank-conflict-free).
//
// Smem byte offsets:
#define XS_OFF   0         // x tf32 [256][132] = 135168 (h1 [256][68] overlays)
#define W1T_OFF  135168    // W1^T tf32 [64][132] = 33792
#define W2T_OFF  168960    // W2^T tf32 [64][68]  = 17408
#define SRC_OFF  186368    // int src[512]: {row[e],col[e]} interleaved = 2048
#define RAD_OFF  188416    // radial[256] = 1024
#define EM_OFF   189440    // edge_mask[256] = 1024
#define W1R_OFF  190464    // W1 radial row [64] = 256
#define B1_OFF   190720    // b1 [64] = 256
#define B2_OFF   190976    // b2 [64] = 256
#define E_SMEM   191232

__global__ __launch_bounds__(256, 1) void edge_kernel(
    const float* __restrict__ h, const float* __restrict__ coord,
    const int* __restrict__ row, const int* __restrict__ col,
    const float* __restrict__ edge_mask,
    const float* __restrict__ W1, const float* __restrict__ b1,
    const float* __restrict__ W2, const float* __restrict__ b2)
{
    extern __shared__ char smem[];
    uint32_t* xSu  = (uint32_t*)(smem + XS_OFF);    // stride 132
    uint32_t* h1u  = (uint32_t*)(smem + XS_OFF);    // stride 68 (overlay)
    uint32_t* W1u  = (uint32_t*)(smem + W1T_OFF);   // stride 132
    uint32_t* W2u  = (uint32_t*)(smem + W2T_OFF);   // stride 68
    int*      srcS = (int*)(smem + SRC_OFF);
    float*    radS = (float*)(smem + RAD_OFF);
    float*    emS  = (float*)(smem + EM_OFF);
    float*    W1rS = (float*)(smem + W1R_OFF);
    float*    b1S  = (float*)(smem + B1_OFF);
    float*    b2S  = (float*)(smem + B2_OFF);

    const int tid  = threadIdx.x;
    const int w    = tid >> 5, lane = tid & 31;
    const int g    = lane >> 2, tg = lane & 3;
    const int ebase = 32 * w;

    // ---- one-time: weights transposed + tf32 ----
    for (int idx = tid; idx < 64 * 128; idx += 256) {   // W1t[n][k] = W1[k][n]
        int n = idx & 63, k = idx >> 6;
        W1u[n * 132 + k] = cvt_tf32(W1[k * 64 + n]);
    }
    for (int idx = tid; idx < 64 * 64; idx += 256) {    // W2t[n][k] = W2[k][n]
        int n = idx & 63, k = idx >> 6;
        W2u[n * 68 + k] = cvt_tf32(W2[k * 64 + n]);
    }
    if (tid < 64) {
        W1rS[tid] = W1[128 * 64 + tid];
        b1S[tid]  = b1[tid];
        b2S[tid]  = b2[tid];
    }
    __syncthreads();

    for (int t0 = blockIdx.x; t0 < NTILES; t0 += gridDim.x) {
        const int e0 = t0 * TILE_E;

        // --- phase 0: stage indices, mask, radial ---
        {
            int e = e0 + tid;
            int rr = row[e], cc = col[e];
            srcS[2 * tid]     = rr;
            srcS[2 * tid + 1] = cc;
            emS[tid] = edge_mask[e];
            float dx = coord[3 * rr]     - coord[3 * cc];
            float dy = coord[3 * rr + 1] - coord[3 * cc + 1];
            float dz = coord[3 * rr + 2] - coord[3 * cc + 2];
            radS[tid] = dx * dx + dy * dy + dz * dz;
        }
        __syncthreads();

        // --- phase 1: gather h rows -> tf32 xS[e][132] ---
        // warp covers 64 src-rows; round: 4 rows, 8 lanes/row (full 128B lines)
        {
            const int qd = lane & 7, rsub = lane >> 3;
            #pragma unroll 4
            for (int j = 0; j < 16; j++) {
                int r = (w << 6) + (j << 2) + rsub;     // 0..511
                int src = srcS[r];
                int eL = r >> 1, s = r & 1;
                const float* hp = h + (size_t)src * NF + 4 * qd;
                float4 v0 = *(const float4*)hp;
                float4 v1 = *(const float4*)(hp + 32);
                uint32_t* dst = xSu + eL * 132 + (s << 6) + 4 * qd;
                *(uint4*)dst =
                    make_uint4(cvt_tf32(v0.x), cvt_tf32(v0.y), cvt_tf32(v0.z), cvt_tf32(v0.w));
                *(uint4*)(dst + 32) =
                    make_uint4(cvt_tf32(v1.x), cvt_tf32(v1.y), cvt_tf32(v1.z), cvt_tf32(v1.w));
            }
        }
        __syncthreads();

        float c[2][8][4];

        // --- phase 2: GEMM1 (K=128, 16 k-steps) ---
        #pragma unroll
        for (int mi = 0; mi < 2; mi++)
            #pragma unroll
            for (int nb = 0; nb < 8; nb++)
                #pragma unroll
                for (int q = 0; q < 4; q++) c[mi][nb][q] = 0.f;
        #pragma unroll 2
        for (int kb = 0; kb < 16; kb++) {
            const int kc = kb * 8 + tg;
            uint32_t a[2][4];
            #pragma unroll
            for (int mi = 0; mi < 2; mi++) {
                int rA = ebase + 16 * mi + g;
                a[mi][0] = xSu[rA * 132 + kc];
                a[mi][1] = xSu[(rA + 8) * 132 + kc];
                a[mi][2] = xSu[rA * 132 + kc + 4];
                a[mi][3] = xSu[(rA + 8) * 132 + kc + 4];
            }
            #pragma unroll
            for (int nb = 0; nb < 8; nb++) {
                uint32_t b0 = W1u[(nb * 8 + g) * 132 + kc];
                uint32_t bb = W1u[(nb * 8 + g) * 132 + kc + 4];
                MMA_TF32(c[0][nb], a[0], b0, bb);
                MMA_TF32(c[1][nb], a[1], b0, bb);
            }
        }
        __syncthreads();   // xS dead; h1 overlay may be written

        // --- phase 3: epilogue1: +rad*W1r + b1, relu -> tf32 h1[e][68] ---
        #pragma unroll
        for (int mi = 0; mi < 2; mi++) {
            int eA = ebase + 16 * mi + g;
            int eB = eA + 8;
            float radA = radS[eA], radB = radS[eB];
            #pragma unroll
            for (int nb = 0; nb < 8; nb++) {
                int j0 = 8 * nb + 2 * tg;
                float w0 = W1rS[j0], w1 = W1rS[j0 + 1];
                float q0 = b1S[j0],  q1 = b1S[j0 + 1];
                float v00 = fmaxf(c[mi][nb][0] + radA * w0 + q0, 0.f);
                float v01 = fmaxf(c[mi][nb][1] + radA * w1 + q1, 0.f);
                float v10 = fmaxf(c[mi][nb][2] + radB * w0 + q0, 0.f);
                float v11 = fmaxf(c[mi][nb][3] + radB * w1 + q1, 0.f);
                *(uint2*)(h1u + eA * 68 + j0) = make_uint2(cvt_tf32(v00), cvt_tf32(v01));
                *(uint2*)(h1u + eB * 68 + j0) = make_uint2(cvt_tf32(v10), cvt_tf32(v11));
            }
        }
        __syncthreads();

        // --- phase 4: GEMM2 (K=64, 8 k-steps) ---
        #pragma unroll
        for (int mi = 0; mi < 2; mi++)
            #pragma unroll
            for (int nb = 0; nb < 8; nb++)
                #pragma unroll
                for (int q = 0; q < 4; q++) c[mi][nb][q] = 0.f;
        #pragma unroll 2
        for (int kb = 0; kb < 8; kb++) {
            const int kc = kb * 8 + tg;
            uint32_t a[2][4];
            #pragma unroll
            for (int mi = 0; mi < 2; mi++) {
                int rA = ebase + 16 * mi + g;
                a[mi][0] = h1u[rA * 68 + kc];
                a[mi][1] = h1u[(rA + 8) * 68 + kc];
                a[mi][2] = h1u[rA * 68 + kc + 4];
                a[mi][3] = h1u[(rA + 8) * 68 + kc + 4];
            }
            #pragma unroll
            for (int nb = 0; nb < 8; nb++) {
                uint32_t b0 = W2u[(nb * 8 + g) * 68 + kc];
                uint32_t bb = W2u[(nb * 8 + g) * 68 + kc + 4];
                MMA_TF32(c[0][nb], a[0], b0, bb);
                MMA_TF32(c[1][nb], a[1], b0, bb);
            }
        }

        // --- phase 5: epilogue2: +b2, relu, *mask, scatter-add ---
        #pragma unroll
        for (int mi = 0; mi < 2; mi++) {
            int eA = ebase + 16 * mi + g;
            int eB = eA + 8;
            int erA = srcS[2 * eA], erB = srcS[2 * eB];
            float emA = emS[eA], emB = emS[eB];
            #pragma unroll
            for (int nb = 0; nb < 8; nb++) {
                int j0 = 8 * nb + 2 * tg;
                float q0 = b2S[j0], q1 = b2S[j0 + 1];
                float v00 = fmaxf(c[mi][nb][0] + q0, 0.f) * emA;
                float v01 = fmaxf(c[mi][nb][1] + q1, 0.f) * emA;
                float v10 = fmaxf(c[mi][nb][2] + q0, 0.f) * emB;
                float v11 = fmaxf(c[mi][nb][3] + q1, 0.f) * emB;
                red_add_v2(g_agg + (size_t)erA * HID + j0, v00, v01);
                red_add_v2(g_agg + (size_t)erB * HID + j0, v10, v11);
            }
        }
        __syncthreads();   // srcS/emS/radS/xS safe to overwrite next tile
    }
}

// ---------------------------------------------------------------------------
// Node kernel (unchanged from passing R7 fp32 version).
#define N_W1D_OFF 0
#define N_W2D_OFF 65536
#define N_XT_OFF  98304
#define N_H1T_OFF 163840
#define N_SMEM    196608

__global__ __launch_bounds__(256, 1) void node_kernel(
    const float* __restrict__ h,
    const float* __restrict__ W1, const float* __restrict__ b1,
    const float* __restrict__ W2, const float* __restrict__ b2,
    float* __restrict__ hout)
{
    extern __shared__ char smem[];
    float2* W1d = (float2*)(smem + N_W1D_OFF);
    float2* W2d = (float2*)(smem + N_W2D_OFF);
    float*  xT  = (float*)(smem + N_XT_OFF);
    float*  h1T = (float*)(smem + N_H1T_OFF);
    float*  oT  = xT;

    const int tid  = threadIdx.x;
    const int warp = tid >> 5, lane = tid & 31;
    const int tx = tid & 15, ty = tid >> 4;
    const int n0 = blockIdx.x * 128;

    for (int i = tid; i < 128 * 64; i += 256) { float ww = W1[i]; W1d[i] = make_float2(ww, ww); }
    for (int i = tid; i < 64 * 64;  i += 256) { float ww = W2[i]; W2d[i] = make_float2(ww, ww); }
    ull bias1[4], bias2[4];
    #pragma unroll
    for (int j = 0; j < 4; j++) {
        float v1 = __ldg(b1 + 4 * ty + j); bias1[j] = pack2(v1, v1);
        float v2 = __ldg(b2 + 4 * ty + j); bias2[j] = pack2(v2, v2);
    }

    {
        #pragma unroll
        for (int it = 0; it < 4; it++) {
            int ug = warp + it * 8;
            bool isH = (ug < 16);
            int kk = isH ? 4 * ug : 4 * (ug - 16);
            int kb = isH ? 4 * ug : 64 + 4 * (ug - 16);
            const float* src = isH ? h : g_agg;
            int na = min(n0 + 4 * lane + 0, NN - 1);
            int nb = min(n0 + 4 * lane + 1, NN - 1);
            int nc = min(n0 + 4 * lane + 2, NN - 1);
            int nd = min(n0 + 4 * lane + 3, NN - 1);
            float4 f0 = *(const float4*)(src + (size_t)na * 64 + kk);
            float4 f1 = *(const float4*)(src + (size_t)nb * 64 + kk);
            float4 f2 = *(const float4*)(src + (size_t)nc * 64 + kk);
            float4 f3 = *(const float4*)(src + (size_t)nd * 64 + kk);
            *(float4*)(xT + (kb + 0) * 128 + 4 * lane) = make_float4(f0.x, f1.x, f2.x, f3.x);
            *(float4*)(xT + (kb + 1) * 128 + 4 * lane) = make_float4(f0.y, f1.y, f2.y, f3.y);
            *(float4*)(xT + (kb + 2) * 128 + 4 * lane) = make_float4(f0.z, f1.z, f2.z, f3.z);
            *(float4*)(xT + (kb + 3) * 128 + 4 * lane) = make_float4(f0.w, f1.w, f2.w, f3.w);
        }
    }
    __syncthreads();

    ull acc[4][4];
    #pragma unroll
    for (int j = 0; j < 4; j++)
        #pragma unroll
        for (int i = 0; i < 4; i++) acc[i][j] = bias1[j];
    #pragma unroll 4
    for (int k = 0; k < 128; k++) {
        ulonglong2 aA = *(const ulonglong2*)(xT + k * 128 + 4 * tx);
        ulonglong2 aB = *(const ulonglong2*)(xT + k * 128 + 64 + 4 * tx);
        ulonglong2 w01 = *(const ulonglong2*)(W1d + k * 64 + 4 * ty);
        ulonglong2 w23 = *(const ulonglong2*)(W1d + k * 64 + 4 * ty + 2);
        ull a[4] = {aA.x, aA.y, aB.x, aB.y};
        ull w[4] = {w01.x, w01.y, w23.x, w23.y};
        #pragma unroll
        for (int i = 0; i < 4; i++)
            #pragma unroll
            for (int j = 0; j < 4; j++)
                acc[i][j] = fma2(a[i], w[j], acc[i][j]);
    }
    #pragma unroll
    for (int j = 0; j < 4; j++) {
        ulonglong2 vA; vA.x = relu2(acc[0][j]); vA.y = relu2(acc[1][j]);
        ulonglong2 vB; vB.x = relu2(acc[2][j]); vB.y = relu2(acc[3][j]);
        *(ulonglong2*)(h1T + (4 * ty + j) * 128 + 4 * tx)      = vA;
        *(ulonglong2*)(h1T + (4 * ty + j) * 128 + 64 + 4 * tx) = vB;
    }
    __syncthreads();

    #pragma unroll
    for (int j = 0; j < 4; j++)
        #pragma unroll
        for (int i = 0; i < 4; i++) acc[i][j] = bias2[j];
    #pragma unroll 4
    for (int k = 0; k < 64; k++) {
        ulonglong2 aA = *(const ulonglong2*)(h1T + k * 128 + 4 * tx);
        ulonglong2 aB = *(const ulonglong2*)(h1T + k * 128 + 64 + 4 * tx);
        ulonglong2 w01 = *(const ulonglong2*)(W2d + k * 64 + 4 * ty);
        ulonglong2 w23 = *(const ulonglong2*)(W2d + k * 64 + 4 * ty + 2);
        ull a[4] = {aA.x, aA.y, aB.x, aB.y};
        ull w[4] = {w01.x, w01.y, w23.x, w23.y};
        #pragma unroll
        for (int i = 0; i < 4; i++)
            #pragma unroll
            for (int j = 0; j < 4; j++)
                acc[i][j] = fma2(a[i], w[j], acc[i][j]);
    }
    #pragma unroll
    for (int j = 0; j < 4; j++) {
        ulonglong2 vA; vA.x = acc[0][j]; vA.y = acc[1][j];
        ulonglong2 vB; vB.x = acc[2][j]; vB.y = acc[3][j];
        *(ulonglong2*)(oT + (4 * ty + j) * 128 + 4 * tx)      = vA;
        *(ulonglong2*)(oT + (4 * ty + j) * 128 + 64 + 4 * tx) = vB;
    }
    __syncthreads();

    {
        int n_l = tid >> 1, half = tid & 1;
        int n = n0 + n_l;
        if (n < NN) {
            const float* hr = h + (size_t)n * NF + half * 32;
            float* orow = hout + (size_t)n * NF + half * 32;
            const float* src = oT + (half * 32) * 128 + n_l;
            #pragma unroll
            for (int jj = 0; jj < 32; jj += 4) {
                float4 hv = *(const float4*)(hr + jj);
                float4 o;
                o.x = src[(jj    ) * 128] + hv.x;
                o.y = src[(jj + 1) * 128] + hv.y;
                o.z = src[(jj + 2) * 128] + hv.z;
                o.w = src[(jj + 3) * 128] + hv.w;
                *(float4*)(orow + jj) = o;
            }
        }
    }
}

// ---------------------------------------------------------------------------
__global__ void copy_coord_kernel(const float* __restrict__ coord,
                                  float* __restrict__ dst) {
    int i = blockIdx.x * blockDim.x + threadIdx.x;
    const int n4 = NN * 3 / 4;
    if (i < n4) ((float4*)dst)[i] = ((const float4*)coord)[i];
}

// ---------------------------------------------------------------------------
extern "C" void kernel_launch(void* const* d_in, const int* in_sizes, int n_in,
                              void* d_out, int out_size) {
    const float* h         = (const float*)d_in[0];
    const float* coord     = (const float*)d_in[1];
    const int*   row       = (const int*)d_in[2];
    const int*   col       = (const int*)d_in[3];
    // d_in[4] = node_mask (unused on the reference path)
    const float* edge_mask = (const float*)d_in[5];
    const float* W_e1 = (const float*)d_in[6];
    const float* b_e1 = (const float*)d_in[7];
    const float* W_e2 = (const float*)d_in[8];
    const float* b_e2 = (const float*)d_in[9];
    const float* W_n1 = (const float*)d_in[10];
    const float* b_n1 = (const float*)d_in[11];
    const float* W_n2 = (const float*)d_in[12];
    const float* b_n2 = (const float*)d_in[13];
    float* out = (float*)d_out;

    cudaFuncSetAttribute(edge_kernel, cudaFuncAttributeMaxDynamicSharedMemorySize, E_SMEM);
    cudaFuncSetAttribute(node_kernel, cudaFuncAttributeMaxDynamicSharedMemorySize, N_SMEM);

    zero_agg_kernel<<<512, 256>>>();
    edge_kernel<<<148, 256, E_SMEM>>>(h, coord, row, col, edge_mask,
                                      W_e1, b_e1, W_e2, b_e2);
    node_kernel<<<(NN + 127) / 128, 256, N_SMEM>>>(h, W_n1, b_n1, W_n2, b_n2, out);
    copy_coord_kernel<<<(NN * 3 / 4 + 255) / 256, 256>>>(coord, out + (size_t)NN * NF);
}

// round 11
// speedup vs baseline: 4.3847x; 1.1980x over previous
#include <cuda_runtime.h>
#include <cstdint>
#include <cstddef>

#define NN 50000
#define EE 800000
#define NF 64
#define HID 64
#define TILE_E 128
#define NTILES (EE / TILE_E)   // 6250 exactly

// Scatter-sum accumulator (allocation-free scratch)
__device__ float g_agg[NN * HID];

typedef unsigned long long ull;

// ===== helpers =====
__device__ __forceinline__ uint32_t cvt_tf32(float f) {
    uint32_t r; asm("cvt.rna.tf32.f32 %0, %1;" : "=r"(r) : "f"(f)); return r;
}
__device__ __forceinline__ void red_add_v2(float* p, float a, float b) {
    asm volatile("red.global.add.v2.f32 [%0], {%1, %2};" :: "l"(p), "f"(a), "f"(b) : "memory");
}
// m16n8k8 tf32 MMA, D += A*B (C==D in-place)
#define MMA_TF32(c, a, b0, b1)                                                  \
    asm volatile("mma.sync.aligned.m16n8k8.row.col.f32.tf32.tf32.f32 "          \
        "{%0,%1,%2,%3}, {%4,%5,%6,%7}, {%8,%9}, {%0,%1,%2,%3};"                 \
        : "+f"((c)[0]), "+f"((c)[1]), "+f"((c)[2]), "+f"((c)[3])                \
        : "r"((a)[0]), "r"((a)[1]), "r"((a)[2]), "r"((a)[3]), "r"(b0), "r"(b1))

// fp32x2 helpers for the node kernel (kept from passing R10)
__device__ __forceinline__ ull pack2(float lo, float hi) {
    ull r;
    asm("mov.b64 %0, {%1, %2};" : "=l"(r) : "r"(__float_as_uint(lo)), "r"(__float_as_uint(hi)));
    return r;
}
__device__ __forceinline__ void unpack2(ull v, float &lo, float &hi) {
    unsigned int a, b;
    asm("mov.b64 {%0, %1}, %2;" : "=r"(a), "=r"(b) : "l"(v));
    lo = __uint_as_float(a); hi = __uint_as_float(b);
}
__device__ __forceinline__ ull fma2(ull a, ull b, ull c) {
    ull d; asm("fma.rn.f32x2 %0, %1, %2, %3;" : "=l"(d) : "l"(a), "l"(b), "l"(c)); return d;
}
__device__ __forceinline__ ull relu2(ull v) {
    float a, b; unpack2(v, a, b);
    return pack2(fmaxf(a, 0.f), fmaxf(b, 0.f));
}

// ---------------------------------------------------------------------------
__global__ void zero_agg_kernel() {
    int i = blockIdx.x * blockDim.x + threadIdx.x;
    const int n4 = NN * HID / 4;
    float4* p = (float4*)g_agg;
    float4 z = make_float4(0.f, 0.f, 0.f, 0.f);
    for (; i < n4; i += gridDim.x * blockDim.x) p[i] = z;
}

// ---------------------------------------------------------------------------
// Edge kernel: persistent, tf32 mma.sync, 2 CTAs/SM for phase overlap.
// Tile = 128 edges, 8 warps, warp owns 16 edge-rows end-to-end (staging,
// MMA-A, epi1, GEMM2) -> only 2 block syncs per tile.
// GEMM1 (K=128) is K-split into two K=64 passes through one 128x68 xS buffer
// (pass 0: h[row], pass 1: h[col]); accumulators persist in registers.
// Strides 68/132 are ≡4 mod 32 -> all fragment LDS accesses conflict-free.
//
// Smem byte offsets (per CTA total 88832 B -> 2 CTAs/SM fit in 227KB):
#define XS_OFF   0         // x tf32 [128][68] = 34816 (h1 overlays after GEMM1)
#define W1T_OFF  34816     // W1^T tf32 [64][132] = 33792
#define W2T_OFF  68608     // W2^T tf32 [64][68]  = 17408
#define SRC_OFF  86016     // int src[256]: {row,col} interleaved = 1024
#define RAD_OFF  87040     // radial[128] = 512
#define EM_OFF   87552     // edge_mask[128] = 512
#define W1R_OFF  88064     // W1 radial row [64] = 256
#define B1_OFF   88320     // b1 [64] = 256
#define B2_OFF   88576     // b2 [64] = 256
#define E_SMEM   88832

__global__ __launch_bounds__(256, 2) void edge_kernel(
    const float* __restrict__ h, const float* __restrict__ coord,
    const int* __restrict__ row, const int* __restrict__ col,
    const float* __restrict__ edge_mask,
    const float* __restrict__ W1, const float* __restrict__ b1,
    const float* __restrict__ W2, const float* __restrict__ b2)
{
    extern __shared__ char smem[];
    uint32_t* xSu  = (uint32_t*)(smem + XS_OFF);    // stride 68
    uint32_t* W1u  = (uint32_t*)(smem + W1T_OFF);   // stride 132
    uint32_t* W2u  = (uint32_t*)(smem + W2T_OFF);   // stride 68
    int*      srcS = (int*)(smem + SRC_OFF);
    float*    radS = (float*)(smem + RAD_OFF);
    float*    emS  = (float*)(smem + EM_OFF);
    float*    W1rS = (float*)(smem + W1R_OFF);
    float*    b1S  = (float*)(smem + B1_OFF);
    float*    b2S  = (float*)(smem + B2_OFF);

    const int tid  = threadIdx.x;
    const int w    = tid >> 5, lane = tid & 31;
    const int g    = lane >> 2, tg = lane & 3;
    const int eb   = 16 * w;              // warp's edge-row base
    const int qd   = lane & 7, rsub = lane >> 3;

    // ---- one-time: weights transposed + tf32 ----
    for (int idx = tid; idx < 64 * 128; idx += 256) {   // W1t[n][k] = W1[k][n]
        int n = idx & 63, k = idx >> 6;
        W1u[n * 132 + k] = cvt_tf32(W1[k * 64 + n]);
    }
    for (int idx = tid; idx < 64 * 64; idx += 256) {    // W2t[n][k] = W2[k][n]
        int n = idx & 63, k = idx >> 6;
        W2u[n * 68 + k] = cvt_tf32(W2[k * 64 + n]);
    }
    if (tid < 64) {
        W1rS[tid] = W1[128 * 64 + tid];
        b1S[tid]  = b1[tid];
        b2S[tid]  = b2[tid];
    }
    __syncthreads();

    for (int t0 = blockIdx.x; t0 < NTILES; t0 += gridDim.x) {
        const int e0 = t0 * TILE_E;

        // --- phase 0: stage indices, mask, radial (cross-warp data) ---
        if (tid < TILE_E) {
            int e = e0 + tid;
            int rr = row[e], cc = col[e];
            srcS[2 * tid]     = rr;
            srcS[2 * tid + 1] = cc;
            emS[tid] = edge_mask[e];
            float dx = coord[3 * rr]     - coord[3 * cc];
            float dy = coord[3 * rr + 1] - coord[3 * cc + 1];
            float dz = coord[3 * rr + 2] - coord[3 * cc + 2];
            radS[tid] = dx * dx + dy * dy + dz * dz;
        }
        __syncthreads();   // sync #1

        // --- prefetch pass-0 gather (h[row]) into registers ---
        float4 p0[4], p1[4];
        #pragma unroll
        for (int j = 0; j < 4; j++) {
            int r = eb + 4 * j + rsub;
            int src = srcS[2 * r];                 // s=0: row side
            const float* hp = h + (size_t)src * NF + 4 * qd;
            p0[j] = *(const float4*)hp;
            p1[j] = *(const float4*)(hp + 32);
        }

        float c1[8][4];
        #pragma unroll
        for (int nb = 0; nb < 8; nb++)
            #pragma unroll
            for (int q = 0; q < 4; q++) c1[nb][q] = 0.f;

        // --- GEMM1: two K=64 passes through xS (warp-local rows) ---
        #pragma unroll
        for (int s = 0; s < 2; s++) {
            // stage this pass's 16 rows (from prefetched regs)
            #pragma unroll
            for (int j = 0; j < 4; j++) {
                int r = eb + 4 * j + rsub;
                uint32_t* dst = xSu + r * 68 + 4 * qd;
                *(uint4*)dst =
                    make_uint4(cvt_tf32(p0[j].x), cvt_tf32(p0[j].y), cvt_tf32(p0[j].z), cvt_tf32(p0[j].w));
                *(uint4*)(dst + 32) =
                    make_uint4(cvt_tf32(p1[j].x), cvt_tf32(p1[j].y), cvt_tf32(p1[j].z), cvt_tf32(p1[j].w));
            }
            __syncwarp();

            // prefetch pass-1 gather (h[col]) during pass-0 MMA
            if (s == 0) {
                #pragma unroll
                for (int j = 0; j < 4; j++) {
                    int r = eb + 4 * j + rsub;
                    int src = srcS[2 * r + 1];     // s=1: col side
                    const float* hp = h + (size_t)src * NF + 4 * qd;
                    p0[j] = *(const float4*)hp;
                    p1[j] = *(const float4*)(hp + 32);
                }
            }

            // MMA pass (K=64, 8 k-steps), accumulate into c1
            #pragma unroll
            for (int kb = 0; kb < 8; kb++) {
                const int kc = kb * 8 + tg;
                uint32_t a[4];
                a[0] = xSu[(eb + g) * 68 + kc];
                a[1] = xSu[(eb + g + 8) * 68 + kc];
                a[2] = xSu[(eb + g) * 68 + kc + 4];
                a[3] = xSu[(eb + g + 8) * 68 + kc + 4];
                #pragma unroll
                for (int nb = 0; nb < 8; nb++) {
                    uint32_t b0 = W1u[(nb * 8 + g) * 132 + 64 * s + kc];
                    uint32_t bb = W1u[(nb * 8 + g) * 132 + 64 * s + kc + 4];
                    MMA_TF32(c1[nb], a, b0, bb);
                }
            }
            __syncwarp();   // warp's MMA reads done before next STS overwrite
        }

        // --- epi1: +rad*W1r + b1, relu -> tf32 h1 (overlay on xS, own rows) ---
        {
            int eA = eb + g, eB = eA + 8;
            float radA = radS[eA], radB = radS[eB];
            #pragma unroll
            for (int nb = 0; nb < 8; nb++) {
                int j0 = 8 * nb + 2 * tg;
                float w0 = W1rS[j0], w1 = W1rS[j0 + 1];
                float q0 = b1S[j0],  q1 = b1S[j0 + 1];
                float v00 = fmaxf(c1[nb][0] + radA * w0 + q0, 0.f);
                float v01 = fmaxf(c1[nb][1] + radA * w1 + q1, 0.f);
                float v10 = fmaxf(c1[nb][2] + radB * w0 + q0, 0.f);
                float v11 = fmaxf(c1[nb][3] + radB * w1 + q1, 0.f);
                *(uint2*)(xSu + eA * 68 + j0) = make_uint2(cvt_tf32(v00), cvt_tf32(v01));
                *(uint2*)(xSu + eB * 68 + j0) = make_uint2(cvt_tf32(v10), cvt_tf32(v11));
            }
        }
        __syncwarp();

        // --- GEMM2 (K=64, 8 k-steps), A = h1 (own rows) ---
        float c2[8][4];
        #pragma unroll
        for (int nb = 0; nb < 8; nb++)
            #pragma unroll
            for (int q = 0; q < 4; q++) c2[nb][q] = 0.f;
        #pragma unroll
        for (int kb = 0; kb < 8; kb++) {
            const int kc = kb * 8 + tg;
            uint32_t a[4];
            a[0] = xSu[(eb + g) * 68 + kc];
            a[1] = xSu[(eb + g + 8) * 68 + kc];
            a[2] = xSu[(eb + g) * 68 + kc + 4];
            a[3] = xSu[(eb + g + 8) * 68 + kc + 4];
            #pragma unroll
            for (int nb = 0; nb < 8; nb++) {
                uint32_t b0 = W2u[(nb * 8 + g) * 68 + kc];
                uint32_t bb = W2u[(nb * 8 + g) * 68 + kc + 4];
                MMA_TF32(c2[nb], a, b0, bb);
            }
        }

        // --- epi2: +b2, relu, *mask, scatter-add ---
        {
            int eA = eb + g, eB = eA + 8;
            int erA = srcS[2 * eA], erB = srcS[2 * eB];
            float emA = emS[eA], emB = emS[eB];
            #pragma unroll
            for (int nb = 0; nb < 8; nb++) {
                int j0 = 8 * nb + 2 * tg;
                float q0 = b2S[j0], q1 = b2S[j0 + 1];
                float v00 = fmaxf(c2[nb][0] + q0, 0.f) * emA;
                float v01 = fmaxf(c2[nb][1] + q1, 0.f) * emA;
                float v10 = fmaxf(c2[nb][2] + q0, 0.f) * emB;
                float v11 = fmaxf(c2[nb][3] + q1, 0.f) * emB;
                red_add_v2(g_agg + (size_t)erA * HID + j0, v00, v01);
                red_add_v2(g_agg + (size_t)erB * HID + j0, v10, v11);
            }
        }
        __syncthreads();   // sync #2: srcS/radS/emS/xS free for next tile
    }
}

// ---------------------------------------------------------------------------
// Node kernel (unchanged from passing R10 fp32 version).
#define N_W1D_OFF 0
#define N_W2D_OFF 65536
#define N_XT_OFF  98304
#define N_H1T_OFF 163840
#define N_SMEM    196608

__global__ __launch_bounds__(256, 1) void node_kernel(
    const float* __restrict__ h,
    const float* __restrict__ W1, const float* __restrict__ b1,
    const float* __restrict__ W2, const float* __restrict__ b2,
    float* __restrict__ hout)
{
    extern __shared__ char smem[];
    float2* W1d = (float2*)(smem + N_W1D_OFF);
    float2* W2d = (float2*)(smem + N_W2D_OFF);
    float*  xT  = (float*)(smem + N_XT_OFF);
    float*  h1T = (float*)(smem + N_H1T_OFF);
    float*  oT  = xT;

    const int tid  = threadIdx.x;
    const int warp = tid >> 5, lane = tid & 31;
    const int tx = tid & 15, ty = tid >> 4;
    const int n0 = blockIdx.x * 128;

    for (int i = tid; i < 128 * 64; i += 256) { float ww = W1[i]; W1d[i] = make_float2(ww, ww); }
    for (int i = tid; i < 64 * 64;  i += 256) { float ww = W2[i]; W2d[i] = make_float2(ww, ww); }
    ull bias1[4], bias2[4];
    #pragma unroll
    for (int j = 0; j < 4; j++) {
        float v1 = __ldg(b1 + 4 * ty + j); bias1[j] = pack2(v1, v1);
        float v2 = __ldg(b2 + 4 * ty + j); bias2[j] = pack2(v2, v2);
    }

    {
        #pragma unroll
        for (int it = 0; it < 4; it++) {
            int ug = warp + it * 8;
            bool isH = (ug < 16);
            int kk = isH ? 4 * ug : 4 * (ug - 16);
            int kb = isH ? 4 * ug : 64 + 4 * (ug - 16);
            const float* src = isH ? h : g_agg;
            int na = min(n0 + 4 * lane + 0, NN - 1);
            int nb = min(n0 + 4 * lane + 1, NN - 1);
            int nc = min(n0 + 4 * lane + 2, NN - 1);
            int nd = min(n0 + 4 * lane + 3, NN - 1);
            float4 f0 = *(const float4*)(src + (size_t)na * 64 + kk);
            float4 f1 = *(const float4*)(src + (size_t)nb * 64 + kk);
            float4 f2 = *(const float4*)(src + (size_t)nc * 64 + kk);
            float4 f3 = *(const float4*)(src + (size_t)nd * 64 + kk);
            *(float4*)(xT + (kb + 0) * 128 + 4 * lane) = make_float4(f0.x, f1.x, f2.x, f3.x);
            *(float4*)(xT + (kb + 1) * 128 + 4 * lane) = make_float4(f0.y, f1.y, f2.y, f3.y);
            *(float4*)(xT + (kb + 2) * 128 + 4 * lane) = make_float4(f0.z, f1.z, f2.z, f3.z);
            *(float4*)(xT + (kb + 3) * 128 + 4 * lane) = make_float4(f0.w, f1.w, f2.w, f3.w);
        }
    }
    __syncthreads();

    ull acc[4][4];
    #pragma unroll
    for (int j = 0; j < 4; j++)
        #pragma unroll
        for (int i = 0; i < 4; i++) acc[i][j] = bias1[j];
    #pragma unroll 4
    for (int k = 0; k < 128; k++) {
        ulonglong2 aA = *(const ulonglong2*)(xT + k * 128 + 4 * tx);
        ulonglong2 aB = *(const ulonglong2*)(xT + k * 128 + 64 + 4 * tx);
        ulonglong2 w01 = *(const ulonglong2*)(W1d + k * 64 + 4 * ty);
        ulonglong2 w23 = *(const ulonglong2*)(W1d + k * 64 + 4 * ty + 2);
        ull a[4] = {aA.x, aA.y, aB.x, aB.y};
        ull w[4] = {w01.x, w01.y, w23.x, w23.y};
        #pragma unroll
        for (int i = 0; i < 4; i++)
            #pragma unroll
            for (int j = 0; j < 4; j++)
                acc[i][j] = fma2(a[i], w[j], acc[i][j]);
    }
    #pragma unroll
    for (int j = 0; j < 4; j++) {
        ulonglong2 vA; vA.x = relu2(acc[0][j]); vA.y = relu2(acc[1][j]);
        ulonglong2 vB; vB.x = relu2(acc[2][j]); vB.y = relu2(acc[3][j]);
        *(ulonglong2*)(h1T + (4 * ty + j) * 128 + 4 * tx)      = vA;
        *(ulonglong2*)(h1T + (4 * ty + j) * 128 + 64 + 4 * tx) = vB;
    }
    __syncthreads();

    #pragma unroll
    for (int j = 0; j < 4; j++)
        #pragma unroll
        for (int i = 0; i < 4; i++) acc[i][j] = bias2[j];
    #pragma unroll 4
    for (int k = 0; k < 64; k++) {
        ulonglong2 aA = *(const ulonglong2*)(h1T + k * 128 + 4 * tx);
        ulonglong2 aB = *(const ulonglong2*)(h1T + k * 128 + 64 + 4 * tx);
        ulonglong2 w01 = *(const ulonglong2*)(W2d + k * 64 + 4 * ty);
        ulonglong2 w23 = *(const ulonglong2*)(W2d + k * 64 + 4 * ty + 2);
        ull a[4] = {aA.x, aA.y, aB.x, aB.y};
        ull w[4] = {w01.x, w01.y, w23.x, w23.y};
        #pragma unroll
        for (int i = 0; i < 4; i++)
            #pragma unroll
            for (int j = 0; j < 4; j++)
                acc[i][j] = fma2(a[i], w[j], acc[i][j]);
    }
    #pragma unroll
    for (int j = 0; j < 4; j++) {
        ulonglong2 vA; vA.x = acc[0][j]; vA.y = acc[1][j];
        ulonglong2 vB; vB.x = acc[2][j]; vB.y = acc[3][j];
        *(ulonglong2*)(oT + (4 * ty + j) * 128 + 4 * tx)      = vA;
        *(ulonglong2*)(oT + (4 * ty + j) * 128 + 64 + 4 * tx) = vB;
    }
    __syncthreads();

    {
        int n_l = tid >> 1, half = tid & 1;
        int n = n0 + n_l;
        if (n < NN) {
            const float* hr = h + (size_t)n * NF + half * 32;
            float* orow = hout + (size_t)n * NF + half * 32;
            const float* src = oT + (half * 32) * 128 + n_l;
            #pragma unroll
            for (int jj = 0; jj < 32; jj += 4) {
                float4 hv = *(const float4*)(hr + jj);
                float4 o;
                o.x = src[(jj    ) * 128] + hv.x;
                o.y = src[(jj + 1) * 128] + hv.y;
                o.z = src[(jj + 2) * 128] + hv.z;
                o.w = src[(jj + 3) * 128] + hv.w;
                *(float4*)(orow + jj) = o;
            }
        }
    }
}

// ---------------------------------------------------------------------------
__global__ void copy_coord_kernel(const float* __restrict__ coord,
                                  float* __restrict__ dst) {
    int i = blockIdx.x * blockDim.x + threadIdx.x;
    const int n4 = NN * 3 / 4;
    if (i < n4) ((float4*)dst)[i] = ((const float4*)coord)[i];
}

// ---------------------------------------------------------------------------
extern "C" void kernel_launch(void* const* d_in, const int* in_sizes, int n_in,
                              void* d_out, int out_size) {
    const float* h         = (const float*)d_in[0];
    const float* coord     = (const float*)d_in[1];
    const int*   row       = (const int*)d_in[2];
    const int*   col       = (const int*)d_in[3];
    // d_in[4] = node_mask (unused on the reference path)
    const float* edge_mask = (const float*)d_in[5];
    const float* W_e1 = (const float*)d_in[6];
    const float* b_e1 = (const float*)d_in[7];
    const float* W_e2 = (const float*)d_in[8];
    const float* b_e2 = (const float*)d_in[9];
    const float* W_n1 = (const float*)d_in[10];
    const float* b_n1 = (const float*)d_in[11];
    const float* W_n2 = (const float*)d_in[12];
    const float* b_n2 = (const float*)d_in[13];
    float* out = (float*)d_out;

    cudaFuncSetAttribute(edge_kernel, cudaFuncAttributeMaxDynamicSharedMemorySize, E_SMEM);
    cudaFuncSetAttribute(node_kernel, cudaFuncAttributeMaxDynamicSharedMemorySize, N_SMEM);

    zero_agg_kernel<<<512, 256>>>();
    edge_kernel<<<296, 256, E_SMEM>>>(h, coord, row, col, edge_mask,
                                      W_e1, b_e1, W_e2, b_e2);
    node_kernel<<<(NN + 127) / 128, 256, N_SMEM>>>(h, W_n1, b_n1, W_n2, b_n2, out);
    copy_coord_kernel<<<(NN * 3 / 4 + 255) / 256, 256>>>(coord, out + (size_t)NN * NF);
}